// round 1
// baseline (speedup 1.0000x reference)
#include <cuda_runtime.h>
#include <cuda_bf16.h>

#define B_   64
#define C_   64
#define HW_  4096
#define NTOK (B_*HW_)          // 262144
#define P_   5
#define E_   4
#define HD_  170
#define TOK  128
#define TPB  256
#define NBLK (NTOK/TOK)        // 2048

// ---------------- scratch (static __device__, allocation-free) ----------------
__device__ float g_emb[B_*C_];
__device__ float g_pw[B_*P_];
__device__ float g_impP[NBLK*E_];
__device__ float g_loadP[NBLK*E_];

__device__ __forceinline__ float gelu_t(float z) {
    // jax.nn.gelu default (approximate=True, tanh form)
    float u = 0.7978845608028654f * (z + 0.044715f * z * z * z);
    return 0.5f * z * (1.0f + tanhf(u));
}

// ---------------- K1: emb[b,c] = mean over HW ----------------
__global__ void k_emb(const float* __restrict__ x) {
    int bc = blockIdx.x;                       // b*64 + c
    const float* p = x + (size_t)bc * HW_;
    float s = 0.f;
    for (int i = threadIdx.x; i < HW_; i += TPB) s += p[i];
    #pragma unroll
    for (int o = 16; o; o >>= 1) s += __shfl_xor_sync(0xffffffffu, s, o);
    __shared__ float red[TPB/32];
    if ((threadIdx.x & 31) == 0) red[threadIdx.x >> 5] = s;
    __syncthreads();
    if (threadIdx.x == 0) {
        float t = 0.f;
        #pragma unroll
        for (int w = 0; w < TPB/32; w++) t += red[w];
        g_emb[bc] = t * (1.0f / HW_);
    }
}

// ---------------- K2: pw[b,p] = softmax(emb @ w_lin + b_lin) ----------------
__global__ void k_pw(const float* __restrict__ w_lin, const float* __restrict__ b_lin) {
    int b = threadIdx.x;
    if (b >= B_) return;
    float lg[P_];
    #pragma unroll
    for (int p = 0; p < P_; p++) lg[p] = b_lin[p];
    for (int c = 0; c < C_; c++) {
        float e = g_emb[b*C_ + c];
        #pragma unroll
        for (int p = 0; p < P_; p++) lg[p] += e * w_lin[c*P_ + p];
    }
    float mx = lg[0];
    #pragma unroll
    for (int p = 1; p < P_; p++) mx = fmaxf(mx, lg[p]);
    float s = 0.f;
    #pragma unroll
    for (int p = 0; p < P_; p++) { lg[p] = expf(lg[p] - mx); s += lg[p]; }
    float inv = 1.0f / s;
    #pragma unroll
    for (int p = 0; p < P_; p++) g_pw[b*P_ + p] = lg[p] * inv;
}

// ---------------- main kernel helpers ----------------
template<int KB>
__device__ __forceinline__ void gemm1_body(
    const float* __restrict__ Ws,          // w1[e] as [c][HD_] fp32 in smem
    const float* __restrict__ ots,         // [c][TOK]
    __nv_bfloat16* __restrict__ Hs,        // [j][TOK] (list-position indexed)
    const int* __restrict__ listTok,
    const float* __restrict__ b1e,
    int m, int warpId, int lane)
{
    int tkn[KB];
    #pragma unroll
    for (int k = 0; k < KB; k++) {
        int i = lane + 32*k;
        tkn[k] = (i < m) ? listTok[i] : 0;
    }
    for (int j0 = warpId*2; j0 < HD_; j0 += 16) {
        float accA[KB], accB[KB];
        #pragma unroll
        for (int k = 0; k < KB; k++) { accA[k] = 0.f; accB[k] = 0.f; }
        const float* wp = Ws + j0;
        #pragma unroll 4
        for (int c = 0; c < C_; c++) {
            float2 w = *(const float2*)(wp + c*HD_);   // j0 even, HD_ even -> 8B aligned
            #pragma unroll
            for (int k = 0; k < KB; k++) {
                float o = ots[c*TOK + tkn[k]];
                accA[k] += w.x * o;
                accB[k] += w.y * o;
            }
        }
        float bb0 = b1e[j0], bb1 = b1e[j0+1];
        #pragma unroll
        for (int k = 0; k < KB; k++) {
            int i = lane + 32*k;
            if (i < m) {
                Hs[ j0   *TOK + i] = __float2bfloat16(gelu_t(accA[k] + bb0));
                Hs[(j0+1)*TOK + i] = __float2bfloat16(gelu_t(accB[k] + bb1));
            }
        }
    }
}

template<int KB>
__device__ __forceinline__ void gemm2_body(
    const float* __restrict__ Ws,          // w2[e] as [j][C_] fp32 in smem
    const __nv_bfloat16* __restrict__ Hs,  // [j][TOK]
    float* __restrict__ Ys,                // [o][TOK]
    const int* __restrict__ listTok,
    const float* __restrict__ listG,
    const float* __restrict__ b2e,
    int m, int warpId, int lane)
{
    for (int o0 = warpId*2; o0 < C_; o0 += 16) {
        float accA[KB], accB[KB];
        #pragma unroll
        for (int k = 0; k < KB; k++) { accA[k] = 0.f; accB[k] = 0.f; }
        const float* wp = Ws + o0;
        #pragma unroll 2
        for (int j = 0; j < HD_; j++) {
            float2 w = *(const float2*)(wp + j*C_);
            #pragma unroll
            for (int k = 0; k < KB; k++) {
                float h = __bfloat162float(Hs[j*TOK + lane + 32*k]);
                accA[k] += w.x * h;
                accB[k] += w.y * h;
            }
        }
        #pragma unroll
        for (int k = 0; k < KB; k++) {
            int i = lane + 32*k;
            if (i < m) {
                int   t = listTok[i];
                float g = listG[i];
                Ys[ o0   *TOK + t] += g * (accA[k] + b2e[o0]);
                Ys[(o0+1)*TOK + t] += g * (accB[k] + b2e[o0+1]);
            }
        }
    }
}

// ---------------- K3: fused conv + gating + sparse MoE + residual ----------------
// smem layout (bytes):
//   ots  : 8192 f  @      0   (32768)
//   Ys   : 8192 f  @  32768   (32768)
//   regA :         @  65536   (43520)  Xs (8192 f) overlaid later by Hs (170*128 bf16)
//   Ws   :         @ 109056   (43520)  staged w_conv / w1[e] / w2[e] fp32
//   misc :         @ 152576   (6160)
#define SMEM_MAIN 158736

__global__ void __launch_bounds__(TPB) k_main(
    const float* __restrict__ x,  const float* __restrict__ sp,
    const float* __restrict__ w_conv, const float* __restrict__ w_gate,
    const float* __restrict__ w1, const float* __restrict__ b1,
    const float* __restrict__ w2, const float* __restrict__ b2,
    float* __restrict__ out)
{
    extern __shared__ char smem[];
    float* ots = (float*)smem;                       // 8192
    float* Ys  = ots + 8192;                         // 8192
    float* Xs  = Ys + 8192;                          // 8192 (regA)
    __nv_bfloat16* Hs = (__nv_bfloat16*)Xs;          // 170*128 bf16 overlays regA
    float* Ws  = (float*)(smem + 109056);            // 10880 f
    char*  misc = smem + 152576;
    float* prompts = (float*)misc;                   // 128
    int*   tokE    = (int*)  (prompts + 128);        // 128
    float* tokG    = (float*)(tokE + 128);           // 256
    int*   listTok = (int*)  (tokG + 256);           // 4*128
    float* listG   = (float*)(listTok + 512);        // 4*128
    int*   cnt     = (int*)  (listG + 512);          // 4

    const int tid  = threadIdx.x;
    const int blk  = blockIdx.x;
    const int b    = blk >> 5;                 // 32 tiles per batch image
    const int hw0  = (blk & 31) * TOK;
    const size_t xbase = (size_t)b * (C_*HW_);

    if (tid < E_) cnt[tid] = 0;

    // load X tile [64][128] (coalesced float4) + stage w_conv into Ws
    for (int i = tid; i < C_*32; i += TPB) {
        int c = i >> 5, q = i & 31;
        float4 v = *(const float4*)(x + xbase + (size_t)c*HW_ + hw0 + q*4);
        *(float4*)&Xs[c*TOK + q*4] = v;
    }
    for (int i = tid; i < C_*C_; i += TPB) Ws[i] = w_conv[i];
    // prompt per token
    if (tid < TOK) {
        float s = 0.f;
        #pragma unroll
        for (int p = 0; p < P_; p++) s += g_pw[b*P_ + p] * sp[p*HW_ + hw0 + tid];
        prompts[tid] = s;
    }
    for (int i = tid; i < 8192; i += TPB) Ys[i] = 0.f;
    __syncthreads();

    // ---- gating: top-2 of 4 per token ----
    if (tid < TOK) {
        float lg0 = 0.f, lg1 = 0.f, lg2 = 0.f, lg3 = 0.f;
        for (int c = 0; c < C_; c++) {
            float xv = Xs[c*TOK + tid];
            float4 wg = *(const float4*)(w_gate + c*4);
            lg0 += xv*wg.x; lg1 += xv*wg.y; lg2 += xv*wg.z; lg3 += xv*wg.w;
        }
        float lv[4] = {lg0, lg1, lg2, lg3};
        float v1 = -1e30f, v2 = -1e30f; int i1 = 0, i2 = 0;
        #pragma unroll
        for (int e = 0; e < E_; e++) {
            if (lv[e] > v1) { v2 = v1; i2 = i1; v1 = lv[e]; i1 = e; }
            else if (lv[e] > v2) { v2 = lv[e]; i2 = e; }
        }
        float g1 = 1.0f / (1.0f + expf(v2 - v1));
        float g2 = 1.0f - g1;
        tokE[tid] = i1 | (i2 << 8);
        tokG[tid*2]   = g1;
        tokG[tid*2+1] = g2;
        int s1 = atomicAdd(&cnt[i1], 1);
        listTok[i1*TOK + s1] = tid;  listG[i1*TOK + s1] = g1;
        int s2 = atomicAdd(&cnt[i2], 1);
        listTok[i2*TOK + s2] = tid;  listG[i2*TOK + s2] = g2;
    }
    __syncthreads();

    // deterministic per-block importance / load partials
    if (tid < E_) {
        float imp = 0.f;
        for (int t = 0; t < TOK; t++) {
            int ee = tokE[t];
            if ((ee & 255) == tid)      imp += tokG[t*2];
            else if ((ee >> 8) == tid)  imp += tokG[t*2+1];
        }
        g_impP[blk*E_ + tid]  = imp;
        g_loadP[blk*E_ + tid] = (float)cnt[tid];
    }

    // ---- 1x1 conv GEMM: ots[o][t] = prompt[t] * sum_c Wc[o][c]*Xs[c][t] ----
    {
        int ty = tid >> 4, tx = tid & 15;
        float acc[4][8];
        #pragma unroll
        for (int a = 0; a < 4; a++)
            #pragma unroll
            for (int k = 0; k < 8; k++) acc[a][k] = 0.f;
        #pragma unroll 4
        for (int c = 0; c < C_; c++) {
            float xv[8];
            #pragma unroll
            for (int k = 0; k < 8; k++) xv[k] = Xs[c*TOK + tx + 16*k];
            float wv[4];
            #pragma unroll
            for (int a = 0; a < 4; a++) wv[a] = Ws[(ty + 16*a)*C_ + c];
            #pragma unroll
            for (int a = 0; a < 4; a++)
                #pragma unroll
                for (int k = 0; k < 8; k++) acc[a][k] += wv[a]*xv[k];
        }
        #pragma unroll
        for (int a = 0; a < 4; a++)
            #pragma unroll
            for (int k = 0; k < 8; k++) {
                int o = ty + 16*a, t = tx + 16*k;
                ots[o*TOK + t] = prompts[t] * acc[a][k];
            }
    }
    __syncthreads();   // Xs dead beyond this point (Hs overlays it)

    const int warpId = tid >> 5, lane = tid & 31;

    // ---- expert loop: sparse gathered MLPs ----
    for (int e = 0; e < E_; e++) {
        // stage w1[e] into smem
        for (int i = tid; i < C_*HD_; i += TPB) Ws[i] = w1[(size_t)e*C_*HD_ + i];
        __syncthreads();
        int m  = cnt[e];
        int KB = (m + 31) >> 5;
        if (m > 0) {
            switch (KB) {
                case 1: gemm1_body<1>(Ws, ots, Hs, listTok + e*TOK, b1 + e*HD_, m, warpId, lane); break;
                case 2: gemm1_body<2>(Ws, ots, Hs, listTok + e*TOK, b1 + e*HD_, m, warpId, lane); break;
                case 3: gemm1_body<3>(Ws, ots, Hs, listTok + e*TOK, b1 + e*HD_, m, warpId, lane); break;
                default: gemm1_body<4>(Ws, ots, Hs, listTok + e*TOK, b1 + e*HD_, m, warpId, lane); break;
            }
        }
        __syncthreads();
        // stage w2[e]
        for (int i = tid; i < HD_*C_; i += TPB) Ws[i] = w2[(size_t)e*HD_*C_ + i];
        __syncthreads();
        if (m > 0) {
            switch (KB) {
                case 1: gemm2_body<1>(Ws, Hs, Ys, listTok + e*TOK, listG + e*TOK, b2 + e*C_, m, warpId, lane); break;
                case 2: gemm2_body<2>(Ws, Hs, Ys, listTok + e*TOK, listG + e*TOK, b2 + e*C_, m, warpId, lane); break;
                case 3: gemm2_body<3>(Ws, Hs, Ys, listTok + e*TOK, listG + e*TOK, b2 + e*C_, m, warpId, lane); break;
                default: gemm2_body<4>(Ws, Hs, Ys, listTok + e*TOK, listG + e*TOK, b2 + e*C_, m, warpId, lane); break;
            }
        }
        __syncthreads();
    }

    // ---- epilogue: out = x + y ----
    for (int i = tid; i < C_*32; i += TPB) {
        int c = i >> 5, q = i & 31;
        size_t gi = xbase + (size_t)c*HW_ + hw0 + q*4;
        float4 xv = *(const float4*)(x + gi);
        float4 yv = *(float4*)&Ys[c*TOK + q*4];
        float4 o4;
        o4.x = xv.x + yv.x; o4.y = xv.y + yv.y;
        o4.z = xv.z + yv.z; o4.w = xv.w + yv.w;
        *(float4*)(out + gi) = o4;
    }
}

// ---------------- K4: loss ----------------
__global__ void k_loss(float* __restrict__ out, int out_size) {
    __shared__ double imp[E_], lod[E_];
    if (threadIdx.x < E_) {
        double si = 0.0, sl = 0.0;
        for (int blk = 0; blk < NBLK; blk++) {
            si += (double)g_impP[blk*E_ + threadIdx.x];
            sl += (double)g_loadP[blk*E_ + threadIdx.x];
        }
        imp[threadIdx.x] = si; lod[threadIdx.x] = sl;
    }
    __syncthreads();
    if (threadIdx.x == 0) {
        double mi = 0.0, ml = 0.0;
        for (int e = 0; e < E_; e++) { mi += imp[e]; ml += lod[e]; }
        mi *= 0.25; ml *= 0.25;
        double vi = 0.0, vl = 0.0;
        for (int e = 0; e < E_; e++) {
            double d = imp[e] - mi; vi += d*d;
            d = lod[e] - ml;        vl += d*d;
        }
        vi *= 0.25; vl *= 0.25;
        double loss = vi / (mi*mi + 1e-10) + vl / (ml*ml + 1e-10);
        if (out_size > NTOK*C_) out[NTOK*C_] = (float)loss;
    }
}

// ---------------- launch ----------------
extern "C" void kernel_launch(void* const* d_in, const int* in_sizes, int n_in,
                              void* d_out, int out_size) {
    (void)in_sizes; (void)n_in;
    const float* x      = (const float*)d_in[0];
    // d_in[1] = text (unused by reference math)
    const float* sp     = (const float*)d_in[2];
    const float* w_lin  = (const float*)d_in[3];
    const float* b_lin  = (const float*)d_in[4];
    const float* w_conv = (const float*)d_in[5];
    const float* w_gate = (const float*)d_in[6];
    const float* w1     = (const float*)d_in[7];
    const float* b1     = (const float*)d_in[8];
    const float* w2     = (const float*)d_in[9];
    const float* b2     = (const float*)d_in[10];
    float* out = (float*)d_out;

    cudaFuncSetAttribute(k_main, cudaFuncAttributeMaxDynamicSharedMemorySize, SMEM_MAIN);

    k_emb<<<B_*C_, TPB>>>(x);
    k_pw<<<1, 64>>>(w_lin, b_lin);
    k_main<<<NBLK, TPB, SMEM_MAIN>>>(x, sp, w_conv, w_gate, w1, b1, w2, b2, out);
    k_loss<<<1, 32>>>(out, out_size);
}

// round 2
// speedup vs baseline: 1.0012x; 1.0012x over previous
#include <cuda_runtime.h>
#include <cuda_bf16.h>

#define B_   64
#define C_   64
#define HW_  4096
#define NTOK (B_*HW_)          // 262144
#define P_   5
#define E_   4
#define HD_  170
#define TOK  128
#define TPB  256
#define NBLK (NTOK/TOK)        // 2048

// ---------------- scratch (static __device__, allocation-free) ----------------
__device__ float g_emb[B_*C_];
__device__ float g_pw[B_*P_];
__device__ float g_impP[NBLK*E_];
__device__ float g_loadP[NBLK*E_];

__device__ __forceinline__ float gelu_t(float z) {
    // jax.nn.gelu default (approximate=True, tanh form)
    float u = 0.7978845608028654f * (z + 0.044715f * z * z * z);
    return 0.5f * z * (1.0f + tanhf(u));
}

// ---------------- K1: emb[b,c] = mean over HW ----------------
__global__ void k_emb(const float* __restrict__ x) {
    int bc = blockIdx.x;                       // b*64 + c
    const float* p = x + (size_t)bc * HW_;
    float s = 0.f;
    for (int i = threadIdx.x; i < HW_; i += TPB) s += p[i];
    #pragma unroll
    for (int o = 16; o; o >>= 1) s += __shfl_xor_sync(0xffffffffu, s, o);
    __shared__ float red[TPB/32];
    if ((threadIdx.x & 31) == 0) red[threadIdx.x >> 5] = s;
    __syncthreads();
    if (threadIdx.x == 0) {
        float t = 0.f;
        #pragma unroll
        for (int w = 0; w < TPB/32; w++) t += red[w];
        g_emb[bc] = t * (1.0f / HW_);
    }
}

// ---------------- K2: pw[b,p] = softmax(emb @ w_lin + b_lin) ----------------
__global__ void k_pw(const float* __restrict__ w_lin, const float* __restrict__ b_lin) {
    int b = threadIdx.x;
    if (b >= B_) return;
    float lg[P_];
    #pragma unroll
    for (int p = 0; p < P_; p++) lg[p] = b_lin[p];
    for (int c = 0; c < C_; c++) {
        float e = g_emb[b*C_ + c];
        #pragma unroll
        for (int p = 0; p < P_; p++) lg[p] += e * w_lin[c*P_ + p];
    }
    float mx = lg[0];
    #pragma unroll
    for (int p = 1; p < P_; p++) mx = fmaxf(mx, lg[p]);
    float s = 0.f;
    #pragma unroll
    for (int p = 0; p < P_; p++) { lg[p] = expf(lg[p] - mx); s += lg[p]; }
    float inv = 1.0f / s;
    #pragma unroll
    for (int p = 0; p < P_; p++) g_pw[b*P_ + p] = lg[p] * inv;
}

// ---------------- main kernel helpers ----------------
template<int KB>
__device__ __forceinline__ void gemm1_body(
    const float* __restrict__ Ws,          // w1[e] as [c][HD_] fp32 in smem
    const float* __restrict__ ots,         // [c][TOK]
    __nv_bfloat16* __restrict__ Hs,        // [j][TOK] (list-position indexed)
    const int* __restrict__ listTok,
    const float* __restrict__ b1e,
    int m, int warpId, int lane)
{
    int tkn[KB];
    #pragma unroll
    for (int k = 0; k < KB; k++) {
        int i = lane + 32*k;
        tkn[k] = (i < m) ? listTok[i] : 0;
    }
    for (int j0 = warpId*2; j0 < HD_; j0 += 16) {
        float accA[KB], accB[KB];
        #pragma unroll
        for (int k = 0; k < KB; k++) { accA[k] = 0.f; accB[k] = 0.f; }
        const float* wp = Ws + j0;
        #pragma unroll 4
        for (int c = 0; c < C_; c++) {
            float2 w = *(const float2*)(wp + c*HD_);   // j0 even, HD_ even -> 8B aligned
            #pragma unroll
            for (int k = 0; k < KB; k++) {
                float o = ots[c*TOK + tkn[k]];
                accA[k] += w.x * o;
                accB[k] += w.y * o;
            }
        }
        float bb0 = b1e[j0], bb1 = b1e[j0+1];
        #pragma unroll
        for (int k = 0; k < KB; k++) {
            int i = lane + 32*k;
            if (i < m) {
                Hs[ j0   *TOK + i] = __float2bfloat16(gelu_t(accA[k] + bb0));
                Hs[(j0+1)*TOK + i] = __float2bfloat16(gelu_t(accB[k] + bb1));
            }
        }
    }
}

template<int KB>
__device__ __forceinline__ void gemm2_body(
    const float* __restrict__ Ws,          // w2[e] as [j][C_] fp32 in smem
    const __nv_bfloat16* __restrict__ Hs,  // [j][TOK]
    float* __restrict__ Ys,                // [o][TOK]
    const int* __restrict__ listTok,
    const float* __restrict__ listG,
    const float* __restrict__ b2e,
    int m, int warpId, int lane)
{
    for (int o0 = warpId*2; o0 < C_; o0 += 16) {
        float accA[KB], accB[KB];
        #pragma unroll
        for (int k = 0; k < KB; k++) { accA[k] = 0.f; accB[k] = 0.f; }
        const float* wp = Ws + o0;
        #pragma unroll 2
        for (int j = 0; j < HD_; j++) {
            float2 w = *(const float2*)(wp + j*C_);
            #pragma unroll
            for (int k = 0; k < KB; k++) {
                float h = __bfloat162float(Hs[j*TOK + lane + 32*k]);
                accA[k] += w.x * h;
                accB[k] += w.y * h;
            }
        }
        #pragma unroll
        for (int k = 0; k < KB; k++) {
            int i = lane + 32*k;
            if (i < m) {
                int   t = listTok[i];
                float g = listG[i];
                Ys[ o0   *TOK + t] += g * (accA[k] + b2e[o0]);
                Ys[(o0+1)*TOK + t] += g * (accB[k] + b2e[o0+1]);
            }
        }
    }
}

// ---------------- K3: fused conv + gating + sparse MoE + residual ----------------
// smem layout (bytes):
//   ots  : 8192 f  @      0   (32768)
//   Ys   : 8192 f  @  32768   (32768)
//   regA :         @  65536   (43520)  Xs (8192 f) overlaid later by Hs (170*128 bf16)
//   Ws   :         @ 109056   (43520)  staged w_conv / w1[e] / w2[e] fp32
//   misc :         @ 152576   (6160)
#define SMEM_MAIN 158736

__global__ void __launch_bounds__(TPB) k_main(
    const float* __restrict__ x,  const float* __restrict__ sp,
    const float* __restrict__ w_conv, const float* __restrict__ w_gate,
    const float* __restrict__ w1, const float* __restrict__ b1,
    const float* __restrict__ w2, const float* __restrict__ b2,
    float* __restrict__ out)
{
    extern __shared__ char smem[];
    float* ots = (float*)smem;                       // 8192
    float* Ys  = ots + 8192;                         // 8192
    float* Xs  = Ys + 8192;                          // 8192 (regA)
    __nv_bfloat16* Hs = (__nv_bfloat16*)Xs;          // 170*128 bf16 overlays regA
    float* Ws  = (float*)(smem + 109056);            // 10880 f
    char*  misc = smem + 152576;
    float* prompts = (float*)misc;                   // 128
    int*   tokE    = (int*)  (prompts + 128);        // 128
    float* tokG    = (float*)(tokE + 128);           // 256
    int*   listTok = (int*)  (tokG + 256);           // 4*128
    float* listG   = (float*)(listTok + 512);        // 4*128
    int*   cnt     = (int*)  (listG + 512);          // 4

    const int tid  = threadIdx.x;
    const int blk  = blockIdx.x;
    const int b    = blk >> 5;                 // 32 tiles per batch image
    const int hw0  = (blk & 31) * TOK;
    const size_t xbase = (size_t)b * (C_*HW_);

    if (tid < E_) cnt[tid] = 0;

    // load X tile [64][128] (coalesced float4) + stage w_conv into Ws
    for (int i = tid; i < C_*32; i += TPB) {
        int c = i >> 5, q = i & 31;
        float4 v = *(const float4*)(x + xbase + (size_t)c*HW_ + hw0 + q*4);
        *(float4*)&Xs[c*TOK + q*4] = v;
    }
    for (int i = tid; i < C_*C_; i += TPB) Ws[i] = w_conv[i];
    // prompt per token
    if (tid < TOK) {
        float s = 0.f;
        #pragma unroll
        for (int p = 0; p < P_; p++) s += g_pw[b*P_ + p] * sp[p*HW_ + hw0 + tid];
        prompts[tid] = s;
    }
    for (int i = tid; i < 8192; i += TPB) Ys[i] = 0.f;
    __syncthreads();

    // ---- gating: top-2 of 4 per token ----
    if (tid < TOK) {
        float lg0 = 0.f, lg1 = 0.f, lg2 = 0.f, lg3 = 0.f;
        for (int c = 0; c < C_; c++) {
            float xv = Xs[c*TOK + tid];
            float4 wg = *(const float4*)(w_gate + c*4);
            lg0 += xv*wg.x; lg1 += xv*wg.y; lg2 += xv*wg.z; lg3 += xv*wg.w;
        }
        float lv[4] = {lg0, lg1, lg2, lg3};
        float v1 = -1e30f, v2 = -1e30f; int i1 = 0, i2 = 0;
        #pragma unroll
        for (int e = 0; e < E_; e++) {
            if (lv[e] > v1) { v2 = v1; i2 = i1; v1 = lv[e]; i1 = e; }
            else if (lv[e] > v2) { v2 = lv[e]; i2 = e; }
        }
        float g1 = 1.0f / (1.0f + expf(v2 - v1));
        float g2 = 1.0f - g1;
        tokE[tid] = i1 | (i2 << 8);
        tokG[tid*2]   = g1;
        tokG[tid*2+1] = g2;
        int s1 = atomicAdd(&cnt[i1], 1);
        listTok[i1*TOK + s1] = tid;  listG[i1*TOK + s1] = g1;
        int s2 = atomicAdd(&cnt[i2], 1);
        listTok[i2*TOK + s2] = tid;  listG[i2*TOK + s2] = g2;
    }
    __syncthreads();

    // deterministic per-block importance / load partials
    if (tid < E_) {
        float imp = 0.f;
        for (int t = 0; t < TOK; t++) {
            int ee = tokE[t];
            if ((ee & 255) == tid)      imp += tokG[t*2];
            else if ((ee >> 8) == tid)  imp += tokG[t*2+1];
        }
        g_impP[blk*E_ + tid]  = imp;
        g_loadP[blk*E_ + tid] = (float)cnt[tid];
    }

    // ---- 1x1 conv GEMM: ots[o][t] = prompt[t] * sum_c Wc[o][c]*Xs[c][t] ----
    {
        int ty = tid >> 4, tx = tid & 15;
        float acc[4][8];
        #pragma unroll
        for (int a = 0; a < 4; a++)
            #pragma unroll
            for (int k = 0; k < 8; k++) acc[a][k] = 0.f;
        #pragma unroll 4
        for (int c = 0; c < C_; c++) {
            float xv[8];
            #pragma unroll
            for (int k = 0; k < 8; k++) xv[k] = Xs[c*TOK + tx + 16*k];
            float wv[4];
            #pragma unroll
            for (int a = 0; a < 4; a++) wv[a] = Ws[(ty + 16*a)*C_ + c];
            #pragma unroll
            for (int a = 0; a < 4; a++)
                #pragma unroll
                for (int k = 0; k < 8; k++) acc[a][k] += wv[a]*xv[k];
        }
        #pragma unroll
        for (int a = 0; a < 4; a++)
            #pragma unroll
            for (int k = 0; k < 8; k++) {
                int o = ty + 16*a, t = tx + 16*k;
                ots[o*TOK + t] = prompts[t] * acc[a][k];
            }
    }
    __syncthreads();   // Xs dead beyond this point (Hs overlays it)

    const int warpId = tid >> 5, lane = tid & 31;

    // ---- expert loop: sparse gathered MLPs ----
    for (int e = 0; e < E_; e++) {
        // stage w1[e] into smem
        for (int i = tid; i < C_*HD_; i += TPB) Ws[i] = w1[(size_t)e*C_*HD_ + i];
        __syncthreads();
        int m  = cnt[e];
        int KB = (m + 31) >> 5;
        if (m > 0) {
            switch (KB) {
                case 1: gemm1_body<1>(Ws, ots, Hs, listTok + e*TOK, b1 + e*HD_, m, warpId, lane); break;
                case 2: gemm1_body<2>(Ws, ots, Hs, listTok + e*TOK, b1 + e*HD_, m, warpId, lane); break;
                case 3: gemm1_body<3>(Ws, ots, Hs, listTok + e*TOK, b1 + e*HD_, m, warpId, lane); break;
                default: gemm1_body<4>(Ws, ots, Hs, listTok + e*TOK, b1 + e*HD_, m, warpId, lane); break;
            }
        }
        __syncthreads();
        // stage w2[e]
        for (int i = tid; i < HD_*C_; i += TPB) Ws[i] = w2[(size_t)e*HD_*C_ + i];
        __syncthreads();
        if (m > 0) {
            switch (KB) {
                case 1: gemm2_body<1>(Ws, Hs, Ys, listTok + e*TOK, listG + e*TOK, b2 + e*C_, m, warpId, lane); break;
                case 2: gemm2_body<2>(Ws, Hs, Ys, listTok + e*TOK, listG + e*TOK, b2 + e*C_, m, warpId, lane); break;
                case 3: gemm2_body<3>(Ws, Hs, Ys, listTok + e*TOK, listG + e*TOK, b2 + e*C_, m, warpId, lane); break;
                default: gemm2_body<4>(Ws, Hs, Ys, listTok + e*TOK, listG + e*TOK, b2 + e*C_, m, warpId, lane); break;
            }
        }
        __syncthreads();
    }

    // ---- epilogue: out = x + y ----
    for (int i = tid; i < C_*32; i += TPB) {
        int c = i >> 5, q = i & 31;
        size_t gi = xbase + (size_t)c*HW_ + hw0 + q*4;
        float4 xv = *(const float4*)(x + gi);
        float4 yv = *(float4*)&Ys[c*TOK + q*4];
        float4 o4;
        o4.x = xv.x + yv.x; o4.y = xv.y + yv.y;
        o4.z = xv.z + yv.z; o4.w = xv.w + yv.w;
        *(float4*)(out + gi) = o4;
    }
}

// ---------------- K4: loss ----------------
__global__ void k_loss(float* __restrict__ out, int out_size) {
    __shared__ double imp[E_], lod[E_];
    if (threadIdx.x < E_) {
        double si = 0.0, sl = 0.0;
        for (int blk = 0; blk < NBLK; blk++) {
            si += (double)g_impP[blk*E_ + threadIdx.x];
            sl += (double)g_loadP[blk*E_ + threadIdx.x];
        }
        imp[threadIdx.x] = si; lod[threadIdx.x] = sl;
    }
    __syncthreads();
    if (threadIdx.x == 0) {
        double mi = 0.0, ml = 0.0;
        for (int e = 0; e < E_; e++) { mi += imp[e]; ml += lod[e]; }
        mi *= 0.25; ml *= 0.25;
        double vi = 0.0, vl = 0.0;
        for (int e = 0; e < E_; e++) {
            double d = imp[e] - mi; vi += d*d;
            d = lod[e] - ml;        vl += d*d;
        }
        vi *= 0.25; vl *= 0.25;
        double loss = vi / (mi*mi + 1e-10) + vl / (ml*ml + 1e-10);
        if (out_size > NTOK*C_) out[NTOK*C_] = (float)loss;
    }
}

// ---------------- launch ----------------
extern "C" void kernel_launch(void* const* d_in, const int* in_sizes, int n_in,
                              void* d_out, int out_size) {
    (void)in_sizes; (void)n_in;
    const float* x      = (const float*)d_in[0];
    // d_in[1] = text (unused by reference math)
    const float* sp     = (const float*)d_in[2];
    const float* w_lin  = (const float*)d_in[3];
    const float* b_lin  = (const float*)d_in[4];
    const float* w_conv = (const float*)d_in[5];
    const float* w_gate = (const float*)d_in[6];
    const float* w1     = (const float*)d_in[7];
    const float* b1     = (const float*)d_in[8];
    const float* w2     = (const float*)d_in[9];
    const float* b2     = (const float*)d_in[10];
    float* out = (float*)d_out;

    cudaFuncSetAttribute(k_main, cudaFuncAttributeMaxDynamicSharedMemorySize, SMEM_MAIN);

    k_emb<<<B_*C_, TPB>>>(x);
    k_pw<<<1, 64>>>(w_lin, b_lin);
    k_main<<<NBLK, TPB, SMEM_MAIN>>>(x, sp, w_conv, w_gate, w1, b1, w2, b2, out);
    k_loss<<<1, 32>>>(out, out_size);
}

// round 3
// speedup vs baseline: 3.9669x; 3.9622x over previous
#include <cuda_runtime.h>
#include <cuda_bf16.h>

#define B_   64
#define C_   64
#define HW_  4096
#define NTOK (B_*HW_)          // 262144
#define P_   5
#define E_   4
#define HD_  170
#define HDP  176               // padded hidden (11 * 16)
#define TOK  128
#define TPB  256
#define NBLK (NTOK/TOK)        // 2048

// ---------------- scratch (static __device__, allocation-free) ----------------
__device__ float g_emb[B_*C_];
__device__ float g_pw[B_*P_];
__device__ float g_impP[NBLK*E_];
__device__ float g_loadP[NBLK*E_];
// bf16 weights, [M][K] row-major, 16B-aligned via uint4 backing
__device__ uint4 g_wc4[ (C_*C_*2)/16 ];            // [o][c]    64x64
__device__ uint4 g_w14[ (E_*HDP*C_*2)/16 ];        // [e][j176][c64]
__device__ uint4 g_w24[ (E_*C_*192*2)/16 ];        // [e][o64][j192] (cols>=176 zero)

__device__ __forceinline__ float gelu_t(float z) {
    float u = 0.7978845608028654f * (z + 0.044715f * z * z * z);
    return 0.5f * z * (1.0f + tanhf(u));
}

// ---------------- K0: weight prep (fp32 -> bf16, transpose, pad) ----------------
__global__ void k_prep(const float* __restrict__ w_conv,
                       const float* __restrict__ w1,
                       const float* __restrict__ w2) {
    int i = blockIdx.x * blockDim.x + threadIdx.x;
    __nv_bfloat16* wc = (__nv_bfloat16*)g_wc4;
    __nv_bfloat16* w1g = (__nv_bfloat16*)g_w14;
    __nv_bfloat16* w2g = (__nv_bfloat16*)g_w24;
    if (i < C_*C_) {
        wc[i] = __float2bfloat16(w_conv[i]);                 // [o][c] direct
    } else if (i < C_*C_ + E_*HDP*C_) {
        int r = i - C_*C_;
        int e = r / (HDP*C_); int r2 = r % (HDP*C_);
        int j = r2 / C_; int c = r2 % C_;
        float v = (j < HD_) ? w1[((size_t)e*C_ + c)*HD_ + j] : 0.f;
        w1g[r] = __float2bfloat16(v);
    } else if (i < C_*C_ + E_*HDP*C_ + E_*C_*192) {
        int r = i - C_*C_ - E_*HDP*C_;
        int e = r / (C_*192); int r2 = r % (C_*192);
        int o = r2 / 192; int j = r2 % 192;
        float v = (j < HD_) ? w2[((size_t)e*HD_ + j)*C_ + o] : 0.f;
        w2g[r] = __float2bfloat16(v);
    }
}

// ---------------- K1: emb[b,c] = mean over HW ----------------
__global__ void k_emb(const float* __restrict__ x) {
    int bc = blockIdx.x;
    const float4* p = (const float4*)(x + (size_t)bc * HW_);
    float s = 0.f;
    for (int i = threadIdx.x; i < HW_/4; i += TPB) {
        float4 v = p[i];
        s += v.x + v.y + v.z + v.w;
    }
    #pragma unroll
    for (int o = 16; o; o >>= 1) s += __shfl_xor_sync(0xffffffffu, s, o);
    __shared__ float red[TPB/32];
    if ((threadIdx.x & 31) == 0) red[threadIdx.x >> 5] = s;
    __syncthreads();
    if (threadIdx.x == 0) {
        float t = 0.f;
        #pragma unroll
        for (int w = 0; w < TPB/32; w++) t += red[w];
        g_emb[bc] = t * (1.0f / HW_);
    }
}

// ---------------- K2: pw[b,p] = softmax(emb @ w_lin + b_lin) ----------------
__global__ void k_pw(const float* __restrict__ w_lin, const float* __restrict__ b_lin) {
    int b = threadIdx.x;
    if (b >= B_) return;
    float lg[P_];
    #pragma unroll
    for (int p = 0; p < P_; p++) lg[p] = b_lin[p];
    for (int c = 0; c < C_; c++) {
        float e = g_emb[b*C_ + c];
        #pragma unroll
        for (int p = 0; p < P_; p++) lg[p] += e * w_lin[c*P_ + p];
    }
    float mx = lg[0];
    #pragma unroll
    for (int p = 1; p < P_; p++) mx = fmaxf(mx, lg[p]);
    float s = 0.f;
    #pragma unroll
    for (int p = 0; p < P_; p++) { lg[p] = expf(lg[p] - mx); s += lg[p]; }
    float inv = 1.0f / s;
    #pragma unroll
    for (int p = 0; p < P_; p++) g_pw[b*P_ + p] = lg[p] * inv;
}

// ---------------- mma helpers ----------------
__device__ __forceinline__ void mma16816(float* c, const unsigned* a, const unsigned* b) {
    asm volatile(
        "mma.sync.aligned.m16n8k16.row.col.f32.bf16.bf16.f32 "
        "{%0,%1,%2,%3},{%4,%5,%6,%7},{%8,%9},{%0,%1,%2,%3};\n"
        : "+f"(c[0]), "+f"(c[1]), "+f"(c[2]), "+f"(c[3])
        : "r"(a[0]), "r"(a[1]), "r"(a[2]), "r"(a[3]), "r"(b[0]), "r"(b[1]));
}
__device__ __forceinline__ void ldmA(unsigned* a, unsigned addr) {
    asm volatile("ldmatrix.sync.aligned.m8n8.x4.shared.b16 {%0,%1,%2,%3},[%4];\n"
        : "=r"(a[0]), "=r"(a[1]), "=r"(a[2]), "=r"(a[3]) : "r"(addr));
}
__device__ __forceinline__ void ldmBT(unsigned* b, unsigned addr) {
    asm volatile("ldmatrix.sync.aligned.m8n8.x4.trans.shared.b16 {%0,%1,%2,%3},[%4];\n"
        : "=r"(b[0]), "=r"(b[1]), "=r"(b[2]), "=r"(b[3]) : "r"(addr));
}
// byte offset of 16B unit (row, cu) in a bf16 matrix with W 16B-units per row, XOR-swizzled
__device__ __forceinline__ unsigned swzB(int row, int cu, int W) {
    return (unsigned)((row * W + (cu ^ (row & 7))) * 16);
}
// byte offset of element (row, tok) in a W=16 activation matrix [row][128 bf16]
__device__ __forceinline__ unsigned actB(int row, int tok) {
    int byte = tok * 2;
    int u = byte >> 4;
    return (unsigned)((row * 16 + (u ^ (row & 7))) * 16 + (byte & 15));
}

// 8-warp tile GEMM inner loop: warp computes m16 x n64 strip, acc[8][4]
__device__ __forceinline__ void gemm_tiles(
    float acc[8][4], unsigned aBase, int aW, unsigned bBase,
    int m0, int nh, int kIters, int r, int q)
{
    for (int kk = 0; kk < kIters; kk++) {
        int k0 = kk * 16;
        unsigned a[4];
        ldmA(a, aBase + swzB(m0 + r + (q & 1) * 8, (k0 >> 3) + (q >> 1), aW));
        #pragma unroll
        for (int g = 0; g < 4; g++) {
            int n0 = nh * 64 + 16 * g;
            unsigned bb[4];
            ldmBT(bb, bBase + swzB(k0 + r + (q & 1) * 8, (n0 >> 3) + (q >> 1), 16));
            mma16816(acc[2*g],     a, bb);
            mma16816(acc[2*g + 1], a, bb + 2);
        }
    }
}

// ---------------- smem layout (bytes) ----------------
#define XF_OFF   0          // fp32 [64][128]                    32768
#define XS_OFF   32768      // bf16 [64][128] swz                16384
#define OT_OFF   49152      // bf16 [64][128] swz                16384
#define HS_OFF   65536      // bf16 [176][128] swz               45056
#define W1_OFF   110592     // bf16 [176][64]  swz (W=8)         22528
#define W2_OFF   133120     // bf16 [64][192]  swz (W=24)        24576
#define WC_OFF   157696     // bf16 [64][64]   swz (W=8)          8192
#define GT_OFF   165888     // fp32 gates [4][128]                2048
#define PR_OFF   167936     // fp32 prompts [128]                  512
#define TE_OFF   168448     // int  tokE [128]                     512
#define TG_OFF   168960     // fp32 tokG [256]                    1024
#define SMEM_MAIN 169984

__global__ void __launch_bounds__(TPB, 1) k_main(
    const float* __restrict__ x,  const float* __restrict__ sp,
    const float* __restrict__ w_gate,
    const float* __restrict__ b1, const float* __restrict__ b2,
    float* __restrict__ out)
{
    extern __shared__ char smem[];
    unsigned sbase = (unsigned)__cvta_generic_to_shared(smem);
    float* Xf      = (float*)(smem + XF_OFF);
    float* gates   = (float*)(smem + GT_OFF);
    float* prompts = (float*)(smem + PR_OFF);
    int*   tokE    = (int*)  (smem + TE_OFF);
    float* tokG    = (float*)(smem + TG_OFF);

    const int tid  = threadIdx.x;
    const int lane = tid & 31, warp = tid >> 5;
    const int r = lane & 7, q = lane >> 3;
    const int blk  = blockIdx.x;
    const int b    = blk >> 5;
    const int hw0  = (blk & 31) * TOK;
    const size_t xbase = (size_t)b * (C_*HW_);

    // ---- stage: X tile (fp32 + bf16 swz), conv weights, prompts, gate zero ----
    for (int u = tid; u < 64*16; u += TPB) {          // 1024 16B units of Xs
        int ch = u >> 4, cu = u & 15;
        const float4* src = (const float4*)(x + xbase + (size_t)ch*HW_ + hw0 + cu*8);
        float4 va = src[0], vb = src[1];
        // fp32 copy
        float4* xf4 = (float4*)(Xf + ch*TOK + cu*8);
        xf4[0] = va; xf4[1] = vb;
        // bf16 swizzled
        __nv_bfloat162 h0 = __float22bfloat162_rn(make_float2(va.x, va.y));
        __nv_bfloat162 h1 = __float22bfloat162_rn(make_float2(va.z, va.w));
        __nv_bfloat162 h2 = __float22bfloat162_rn(make_float2(vb.x, vb.y));
        __nv_bfloat162 h3 = __float22bfloat162_rn(make_float2(vb.z, vb.w));
        uint4 pk = { *(unsigned*)&h0, *(unsigned*)&h1, *(unsigned*)&h2, *(unsigned*)&h3 };
        *(uint4*)(smem + XS_OFF + swzB(ch, cu, 16)) = pk;
    }
    for (int u = tid; u < 64*8; u += TPB) {           // Wc: 512 units
        int row = u >> 3, cu = u & 7;
        *(uint4*)(smem + WC_OFF + swzB(row, cu, 8)) = g_wc4[u];
    }
    if (tid < TOK) {
        float s = 0.f;
        #pragma unroll
        for (int p = 0; p < P_; p++) s += g_pw[b*P_ + p] * sp[p*HW_ + hw0 + tid];
        prompts[tid] = s;
    }
    for (int i = tid; i < E_*TOK; i += TPB) gates[i] = 0.f;
    __syncthreads();

    // ---- gating: fp32 top-2 (exact, from Xf) ----
    if (tid < TOK) {
        float lg0 = 0.f, lg1 = 0.f, lg2 = 0.f, lg3 = 0.f;
        for (int c = 0; c < C_; c++) {
            float xv = Xf[c*TOK + tid];
            float4 wg = *(const float4*)(w_gate + c*4);
            lg0 += xv*wg.x; lg1 += xv*wg.y; lg2 += xv*wg.z; lg3 += xv*wg.w;
        }
        float lv[4] = {lg0, lg1, lg2, lg3};
        float v1 = -1e30f, v2 = -1e30f; int i1 = 0, i2 = 0;
        #pragma unroll
        for (int e = 0; e < E_; e++) {
            if (lv[e] > v1) { v2 = v1; i2 = i1; v1 = lv[e]; i1 = e; }
            else if (lv[e] > v2) { v2 = lv[e]; i2 = e; }
        }
        float g1 = 1.0f / (1.0f + expf(v2 - v1));
        float g2 = 1.0f - g1;
        tokE[tid] = i1 | (i2 << 8);
        tokG[tid*2]   = g1;
        tokG[tid*2+1] = g2;
        gates[i1*TOK + tid] = g1;
        gates[i2*TOK + tid] = g2;
    }
    __syncthreads();

    // loss partials (deterministic per-block)
    if (tid < E_) {
        float imp = 0.f; int cnt = 0;
        for (int t = 0; t < TOK; t++) {
            int ee = tokE[t];
            if ((ee & 255) == tid)      { imp += tokG[t*2];   cnt++; }
            else if ((ee >> 8) == tid)  { imp += tokG[t*2+1]; cnt++; }
        }
        g_impP[blk*E_ + tid]  = imp;
        g_loadP[blk*E_ + tid] = (float)cnt;
    }

    // ---- conv: OT[o][t] = prompt[t] * sum_c Wc[o][c] * X[c][t] ----
    const int sm_ = warp & 3, nh_ = warp >> 2;     // warp's m-strip / n-half
    {
        float acc[8][4];
        #pragma unroll
        for (int i = 0; i < 8; i++)
            #pragma unroll
            for (int j = 0; j < 4; j++) acc[i][j] = 0.f;
        gemm_tiles(acc, sbase + WC_OFF, 8, sbase + XS_OFF, sm_*16, nh_, 4, r, q);
        // epilogue -> OTs (bf16, prompt-scaled)
        int m0 = sm_*16 + lane/4;
        #pragma unroll
        for (int i = 0; i < 8; i++) {
            int t = nh_*64 + 8*i + 2*(lane & 3);
            float p0 = prompts[t], p1 = prompts[t+1];
            __nv_bfloat162 lo = __float22bfloat162_rn(make_float2(acc[i][0]*p0, acc[i][1]*p1));
            __nv_bfloat162 hi = __float22bfloat162_rn(make_float2(acc[i][2]*p0, acc[i][3]*p1));
            *(unsigned*)(smem + OT_OFF + actB(m0,     t)) = *(unsigned*)&lo;
            *(unsigned*)(smem + OT_OFF + actB(m0 + 8, t)) = *(unsigned*)&hi;
        }
    }

    // ---- expert loop: dense gemm1 (gelu+gate) then gemm2 (reg-accum) ----
    float accD[8][4];
    #pragma unroll
    for (int i = 0; i < 8; i++)
        #pragma unroll
        for (int j = 0; j < 4; j++) accD[i][j] = 0.f;

    for (int e = 0; e < E_; e++) {
        // stage W1(e) [176][64] and W2(e) [64][192] bf16, swizzled
        for (int u = tid; u < HDP*8; u += TPB) {              // 1408 units
            int row = u >> 3, cu = u & 7;
            *(uint4*)(smem + W1_OFF + swzB(row, cu, 8)) = g_w14[e*(HDP*8) + u];
        }
        for (int u = tid; u < 64*24; u += TPB) {              // 1536 units
            int row = u / 24, cu = u % 24;
            *(uint4*)(smem + W2_OFF + swzB(row, cu, 24)) = g_w24[e*(64*24) + u];
        }
        __syncthreads();

        // gemm1: H[j][t] = gelu(sum_c OT[c][t] W1[j][c] + b1[j]) * gates[e][t]
        for (int item = warp; item < 22; item += 8) {
            int ms = item >> 1, nh = item & 1;
            float acc[8][4];
            #pragma unroll
            for (int i = 0; i < 8; i++)
                #pragma unroll
                for (int j = 0; j < 4; j++) acc[i][j] = 0.f;
            gemm_tiles(acc, sbase + W1_OFF, 8, sbase + OT_OFF, ms*16, nh, 4, r, q);
            int j0 = ms*16 + lane/4, j1 = j0 + 8;
            float b1a = (j0 < HD_) ? b1[e*HD_ + j0] : 0.f;
            float b1b = (j1 < HD_) ? b1[e*HD_ + j1] : 0.f;
            #pragma unroll
            for (int i = 0; i < 8; i++) {
                int t = nh*64 + 8*i + 2*(lane & 3);
                float g0 = gates[e*TOK + t], g1 = gates[e*TOK + t + 1];
                float v0 = gelu_t(acc[i][0] + b1a) * g0;
                float v1 = gelu_t(acc[i][1] + b1a) * g1;
                float v2 = gelu_t(acc[i][2] + b1b) * g0;
                float v3 = gelu_t(acc[i][3] + b1b) * g1;
                __nv_bfloat162 lo = __float22bfloat162_rn(make_float2(v0, v1));
                __nv_bfloat162 hi = __float22bfloat162_rn(make_float2(v2, v3));
                *(unsigned*)(smem + HS_OFF + actB(j0, t)) = *(unsigned*)&lo;
                *(unsigned*)(smem + HS_OFF + actB(j1, t)) = *(unsigned*)&hi;
            }
        }
        __syncthreads();

        // gemm2: accD += W2[o][j] * Hg[j][t]   (K = 176)
        gemm_tiles(accD, sbase + W2_OFF, 24, sbase + HS_OFF, sm_*16, nh_, 11, r, q);
        __syncthreads();
    }

    // ---- epilogue: out = x + y + sum_e gates*b2 ----
    {
        int o0 = sm_*16 + lane/4, o1 = o0 + 8;
        #pragma unroll
        for (int i = 0; i < 8; i++) {
            int t = nh_*64 + 8*i + 2*(lane & 3);
            float bb00 = 0.f, bb01 = 0.f, bb10 = 0.f, bb11 = 0.f;
            #pragma unroll
            for (int e = 0; e < E_; e++) {
                float ge0 = gates[e*TOK + t], ge1 = gates[e*TOK + t + 1];
                float w0 = b2[e*C_ + o0], w1v = b2[e*C_ + o1];
                bb00 += ge0 * w0; bb01 += ge1 * w0;
                bb10 += ge0 * w1v; bb11 += ge1 * w1v;
            }
            float2 r0, r1;
            r0.x = Xf[o0*TOK + t]   + accD[i][0] + bb00;
            r0.y = Xf[o0*TOK + t+1] + accD[i][1] + bb01;
            r1.x = Xf[o1*TOK + t]   + accD[i][2] + bb10;
            r1.y = Xf[o1*TOK + t+1] + accD[i][3] + bb11;
            *(float2*)(out + xbase + (size_t)o0*HW_ + hw0 + t) = r0;
            *(float2*)(out + xbase + (size_t)o1*HW_ + hw0 + t) = r1;
        }
    }
}

// ---------------- K4: loss (parallel, deterministic) ----------------
__global__ void k_loss(float* __restrict__ out, int out_size) {
    __shared__ double imp[E_], lod[E_];
    int warp = threadIdx.x >> 5, lane = threadIdx.x & 31;
    if (warp < E_) {
        double si = 0.0, sl = 0.0;
        for (int blk = lane; blk < NBLK; blk += 32) {
            si += (double)g_impP[blk*E_ + warp];
            sl += (double)g_loadP[blk*E_ + warp];
        }
        #pragma unroll
        for (int o = 16; o; o >>= 1) {
            si += __shfl_down_sync(0xffffffffu, si, o);
            sl += __shfl_down_sync(0xffffffffu, sl, o);
        }
        if (lane == 0) { imp[warp] = si; lod[warp] = sl; }
    }
    __syncthreads();
    if (threadIdx.x == 0) {
        double mi = 0.0, ml = 0.0;
        for (int e = 0; e < E_; e++) { mi += imp[e]; ml += lod[e]; }
        mi *= 0.25; ml *= 0.25;
        double vi = 0.0, vl = 0.0;
        for (int e = 0; e < E_; e++) {
            double d = imp[e] - mi; vi += d*d;
            d = lod[e] - ml;        vl += d*d;
        }
        vi *= 0.25; vl *= 0.25;
        double loss = vi / (mi*mi + 1e-10) + vl / (ml*ml + 1e-10);
        if (out_size > NTOK*C_) out[NTOK*C_] = (float)loss;
    }
}

// ---------------- launch ----------------
extern "C" void kernel_launch(void* const* d_in, const int* in_sizes, int n_in,
                              void* d_out, int out_size) {
    (void)in_sizes; (void)n_in;
    const float* x      = (const float*)d_in[0];
    const float* sp     = (const float*)d_in[2];
    const float* w_lin  = (const float*)d_in[3];
    const float* b_lin  = (const float*)d_in[4];
    const float* w_conv = (const float*)d_in[5];
    const float* w_gate = (const float*)d_in[6];
    const float* w1     = (const float*)d_in[7];
    const float* b1     = (const float*)d_in[8];
    const float* w2     = (const float*)d_in[9];
    const float* b2     = (const float*)d_in[10];
    float* out = (float*)d_out;

    cudaFuncSetAttribute(k_main, cudaFuncAttributeMaxDynamicSharedMemorySize, SMEM_MAIN);

    int prep_total = C_*C_ + E_*HDP*C_ + E_*C_*192;
    k_prep<<<(prep_total + 255)/256, 256>>>(w_conv, w1, w2);
    k_emb<<<B_*C_, TPB>>>(x);
    k_pw<<<1, 64>>>(w_lin, b_lin);
    k_main<<<NBLK, TPB, SMEM_MAIN>>>(x, sp, w_gate, b1, b2, out);
    k_loss<<<1, 128>>>(out, out_size);
}

// round 4
// speedup vs baseline: 8.1761x; 2.0611x over previous
#include <cuda_runtime.h>
#include <cuda_bf16.h>
#include <cuda_pipeline.h>

#define B_   64
#define C_   64
#define HW_  4096
#define NTOK (B_*HW_)          // 262144
#define P_   5
#define E_   4
#define HD_  170
#define HDP  176               // padded hidden (11 * 16)
#define TOK  256
#define TPB  512
#define NBLK (NTOK/TOK)        // 1024

// ---------------- scratch (static __device__, allocation-free) ----------------
__device__ float g_emb[B_*C_];
__device__ float g_pw[B_*P_];
__device__ float g_impP[NBLK*E_];
__device__ float g_loadP[NBLK*E_];
// bf16 weights, [M][K] row-major, 16B-aligned via uint4 backing
__device__ uint4 g_wc4[ (C_*C_*2)/16 ];            // [o][c]    64x64
__device__ uint4 g_w14[ (E_*HDP*C_*2)/16 ];        // [e][j176][c64]
__device__ uint4 g_w24[ (E_*C_*192*2)/16 ];        // [e][o64][j192] (cols>=176 zero)

__device__ __forceinline__ float gelu_t(float z) {
    // tanh-form gelu with fast exp: tanh(u) = sign(u)*(1-e^-2|u|)/(1+e^-2|u|)
    float u  = 0.7978845608028654f * z * (1.0f + 0.044715f * z * z);
    float eu = __expf(-2.0f * fabsf(u));
    float th = __fdividef(1.0f - eu, 1.0f + eu);
    th = copysignf(th, u);
    return 0.5f * z * (1.0f + th);
}

// ---------------- K0: weight prep (fp32 -> bf16, transpose, pad) ----------------
__global__ void k_prep(const float* __restrict__ w_conv,
                       const float* __restrict__ w1,
                       const float* __restrict__ w2) {
    int i = blockIdx.x * blockDim.x + threadIdx.x;
    __nv_bfloat16* wc = (__nv_bfloat16*)g_wc4;
    __nv_bfloat16* w1g = (__nv_bfloat16*)g_w14;
    __nv_bfloat16* w2g = (__nv_bfloat16*)g_w24;
    if (i < C_*C_) {
        wc[i] = __float2bfloat16(w_conv[i]);
    } else if (i < C_*C_ + E_*HDP*C_) {
        int r = i - C_*C_;
        int e = r / (HDP*C_); int r2 = r % (HDP*C_);
        int j = r2 / C_; int c = r2 % C_;
        float v = (j < HD_) ? w1[((size_t)e*C_ + c)*HD_ + j] : 0.f;
        w1g[r] = __float2bfloat16(v);
    } else if (i < C_*C_ + E_*HDP*C_ + E_*C_*192) {
        int r = i - C_*C_ - E_*HDP*C_;
        int e = r / (C_*192); int r2 = r % (C_*192);
        int o = r2 / 192; int j = r2 % 192;
        float v = (j < HD_) ? w2[((size_t)e*HD_ + j)*C_ + o] : 0.f;
        w2g[r] = __float2bfloat16(v);
    }
}

// ---------------- K1: emb[b,c] = mean over HW ----------------
__global__ void k_emb(const float* __restrict__ x) {
    int bc = blockIdx.x;
    const float4* p = (const float4*)(x + (size_t)bc * HW_);
    float s = 0.f;
    for (int i = threadIdx.x; i < HW_/4; i += blockDim.x) {
        float4 v = p[i];
        s += v.x + v.y + v.z + v.w;
    }
    #pragma unroll
    for (int o = 16; o; o >>= 1) s += __shfl_xor_sync(0xffffffffu, s, o);
    __shared__ float red[TPB/32];
    if ((threadIdx.x & 31) == 0) red[threadIdx.x >> 5] = s;
    __syncthreads();
    if (threadIdx.x == 0) {
        float t = 0.f;
        for (int w = 0; w < (int)(blockDim.x >> 5); w++) t += red[w];
        g_emb[bc] = t * (1.0f / HW_);
    }
}

// ---------------- K2: pw[b,p] = softmax(emb @ w_lin + b_lin) ----------------
__global__ void k_pw(const float* __restrict__ w_lin, const float* __restrict__ b_lin) {
    int b = threadIdx.x;
    if (b >= B_) return;
    float lg[P_];
    #pragma unroll
    for (int p = 0; p < P_; p++) lg[p] = b_lin[p];
    for (int c = 0; c < C_; c++) {
        float e = g_emb[b*C_ + c];
        #pragma unroll
        for (int p = 0; p < P_; p++) lg[p] += e * w_lin[c*P_ + p];
    }
    float mx = lg[0];
    #pragma unroll
    for (int p = 1; p < P_; p++) mx = fmaxf(mx, lg[p]);
    float s = 0.f;
    #pragma unroll
    for (int p = 0; p < P_; p++) { lg[p] = expf(lg[p] - mx); s += lg[p]; }
    float inv = 1.0f / s;
    #pragma unroll
    for (int p = 0; p < P_; p++) g_pw[b*P_ + p] = lg[p] * inv;
}

// ---------------- mma helpers ----------------
__device__ __forceinline__ void mma16816(float* c, const unsigned* a, const unsigned* b) {
    asm volatile(
        "mma.sync.aligned.m16n8k16.row.col.f32.bf16.bf16.f32 "
        "{%0,%1,%2,%3},{%4,%5,%6,%7},{%8,%9},{%0,%1,%2,%3};\n"
        : "+f"(c[0]), "+f"(c[1]), "+f"(c[2]), "+f"(c[3])
        : "r"(a[0]), "r"(a[1]), "r"(a[2]), "r"(a[3]), "r"(b[0]), "r"(b[1]));
}
__device__ __forceinline__ void ldmA(unsigned* a, unsigned addr) {
    asm volatile("ldmatrix.sync.aligned.m8n8.x4.shared.b16 {%0,%1,%2,%3},[%4];\n"
        : "=r"(a[0]), "=r"(a[1]), "=r"(a[2]), "=r"(a[3]) : "r"(addr));
}
__device__ __forceinline__ void ldmBT(unsigned* b, unsigned addr) {
    asm volatile("ldmatrix.sync.aligned.m8n8.x4.trans.shared.b16 {%0,%1,%2,%3},[%4];\n"
        : "=r"(b[0]), "=r"(b[1]), "=r"(b[2]), "=r"(b[3]) : "r"(addr));
}
// byte offset of 16B unit (row, cu) in a bf16 matrix with W 16B-units per row, XOR-swizzled
__device__ __forceinline__ unsigned swzB(int row, int cu, int W) {
    return (unsigned)((row * W + (cu ^ (row & 7))) * 16);
}
// byte offset of element (row, tok) in an activation matrix [row][W*8 bf16], swizzled
__device__ __forceinline__ unsigned actB(int row, int tok, int W) {
    int u = tok >> 3;
    return (unsigned)((row * W + (u ^ (row & 7))) * 16 + (tok & 7) * 2);
}

// warp computes m16 x n64 strip: acc[8][4] += A[m0:m0+16, :16k] * B[:, n0:n0+64]
__device__ __forceinline__ void gemm_tiles(
    float acc[8][4], unsigned aBase, int aW, unsigned bBase, int bW,
    int m0, int n0, int kIters, int r, int q)
{
    for (int kk = 0; kk < kIters; kk++) {
        int k0 = kk * 16;
        unsigned a[4];
        ldmA(a, aBase + swzB(m0 + r + (q & 1) * 8, (k0 >> 3) + (q >> 1), aW));
        #pragma unroll
        for (int g = 0; g < 4; g++) {
            int n0g = n0 + 16 * g;
            unsigned bb[4];
            ldmBT(bb, bBase + swzB(k0 + r + (q & 1) * 8, (n0g >> 3) + (q >> 1), bW));
            mma16816(acc[2*g],     a, bb);
            mma16816(acc[2*g + 1], a, bb + 2);
        }
    }
}

// ---------------- smem layout (bytes) ----------------
#define XS_OFF   0          // bf16 [64][256]  swz (W=32)   32768
#define OT_OFF   32768      // bf16 [64][256]  swz (W=32)   32768
#define HS_OFF   65536      // bf16 [176][256] swz (W=32)   90112  (gating partials live here early)
#define W1_OFF   155648     // bf16 [176][64]  swz (W=8)    22528
#define W2_OFF   178176     // bf16 [64][192]  swz (W=24)   24576
#define WC_OFF   202752     // bf16 [64][64]   swz (W=8)     8192
#define GT_OFF   210944     // fp32 gates [4][256]           4096
#define PR_OFF   215040     // fp32 prompts [256]            1024
#define SMEM_MAIN 216064

__device__ __forceinline__ void stage_wc(char* smem, int tid) {
    int u = tid;                                  // 512 units, one per thread
    int row = u >> 3, cu = u & 7;
    __pipeline_memcpy_async(smem + WC_OFF + swzB(row, cu, 8), g_wc4 + u, 16);
}
__device__ __forceinline__ void stage_w1(char* smem, int e, int tid) {
    for (int u = tid; u < HDP*8; u += TPB) {      // 1408 units
        int row = u >> 3, cu = u & 7;
        __pipeline_memcpy_async(smem + W1_OFF + swzB(row, cu, 8), g_w14 + e*(HDP*8) + u, 16);
    }
}
__device__ __forceinline__ void stage_w2(char* smem, int e, int tid) {
    for (int u = tid; u < 64*24; u += TPB) {      // 1536 units
        int row = u / 24, cu = u % 24;
        __pipeline_memcpy_async(smem + W2_OFF + swzB(row, cu, 24), g_w24 + e*(64*24) + u, 16);
    }
}

__global__ void __launch_bounds__(TPB, 1) k_main(
    const float* __restrict__ x,  const float* __restrict__ sp,
    const float* __restrict__ w_gate,
    const float* __restrict__ b1, const float* __restrict__ b2,
    float* __restrict__ out)
{
    extern __shared__ char smem[];
    unsigned sbase = (unsigned)__cvta_generic_to_shared(smem);
    float* gates   = (float*)(smem + GT_OFF);
    float* prompts = (float*)(smem + PR_OFF);

    const int tid  = threadIdx.x;
    const int lane = tid & 31, warp = tid >> 5;
    const int r = lane & 7, q = lane >> 3;
    const int blk  = blockIdx.x;
    const int b    = blk >> 4;                 // 16 tiles of 256 per batch image
    const int hw0  = (blk & 15) * TOK;
    const size_t xbase = (size_t)b * (C_*HW_);

    // ---- async weight prologue: WC + W1(0), then W2(0) ----
    stage_wc(smem, tid);
    stage_w1(smem, 0, tid);
    __pipeline_commit();                 // G: WC+W1(0)
    stage_w2(smem, 0, tid);
    __pipeline_commit();                 // G: W2(0)

    // ---- stage X tile as bf16 swizzled [64][256] ----
    for (int u = tid; u < 64*32; u += TPB) {
        int ch = u >> 5, cu = u & 31;
        const float4* src = (const float4*)(x + xbase + (size_t)ch*HW_ + hw0 + cu*8);
        float4 va = src[0], vb = src[1];
        __nv_bfloat162 h0 = __float22bfloat162_rn(make_float2(va.x, va.y));
        __nv_bfloat162 h1 = __float22bfloat162_rn(make_float2(va.z, va.w));
        __nv_bfloat162 h2 = __float22bfloat162_rn(make_float2(vb.x, vb.y));
        __nv_bfloat162 h3 = __float22bfloat162_rn(make_float2(vb.z, vb.w));
        uint4 pk = { *(unsigned*)&h0, *(unsigned*)&h1, *(unsigned*)&h2, *(unsigned*)&h3 };
        *(uint4*)(smem + XS_OFF + swzB(ch, cu, 32)) = pk;
    }
    // prompts
    if (tid < TOK) {
        float s = 0.f;
        #pragma unroll
        for (int p = 0; p < P_; p++) s += g_pw[b*P_ + p] * sp[p*HW_ + hw0 + tid];
        prompts[tid] = s;
    }
    // gates zero
    for (int i = tid; i < E_*TOK; i += TPB) gates[i] = 0.f;

    // ---- gating partials: fp32 logits straight from global x (exact) ----
    {
        int t = tid & 255, h = tid >> 8;
        float lg0 = 0.f, lg1 = 0.f, lg2 = 0.f, lg3 = 0.f;
        const float* xp = x + xbase + (size_t)(h*32)*HW_ + hw0 + t;
        #pragma unroll 8
        for (int c = 0; c < 32; c++) {
            float xv = xp[(size_t)c*HW_];
            float4 wg = *(const float4*)(w_gate + (h*32 + c)*4);
            lg0 += xv*wg.x; lg1 += xv*wg.y; lg2 += xv*wg.z; lg3 += xv*wg.w;
        }
        float4 pk = make_float4(lg0, lg1, lg2, lg3);
        *(float4*)(smem + HS_OFF + tid*16) = pk;    // partials in HS area (free until gemm1)
    }
    __pipeline_wait_prior(1);            // WC + W1(0) landed
    __syncthreads();

    // ---- gating combine + top2 ----
    if (tid < TOK) {
        float4 pa = *(float4*)(smem + HS_OFF + tid*16);
        float4 pb = *(float4*)(smem + HS_OFF + (256 + tid)*16);
        float lv[4] = { pa.x + pb.x, pa.y + pb.y, pa.z + pb.z, pa.w + pb.w };
        float v1 = -1e30f, v2 = -1e30f; int i1 = 0, i2 = 0;
        #pragma unroll
        for (int e = 0; e < E_; e++) {
            if (lv[e] > v1) { v2 = v1; i2 = i1; v1 = lv[e]; i1 = e; }
            else if (lv[e] > v2) { v2 = lv[e]; i2 = e; }
        }
        float g1 = 1.0f / (1.0f + expf(v2 - v1));
        float g2 = 1.0f - g1;
        gates[i1*TOK + tid] = g1;
        gates[i2*TOK + tid] = g2;
    }
    __syncthreads();

    // ---- loss partials: warp e reduces gates[e][*] ----
    if (warp < E_) {
        float imp = 0.f; int cnt = 0;
        for (int t = lane; t < TOK; t += 32) {
            float g = gates[warp*TOK + t];
            imp += g; cnt += (g > 0.f);
        }
        #pragma unroll
        for (int o = 16; o; o >>= 1) {
            imp += __shfl_xor_sync(0xffffffffu, imp, o);
            cnt += __shfl_xor_sync(0xffffffffu, cnt, o);
        }
        if (lane == 0) {
            g_impP[blk*E_ + warp]  = imp;
            g_loadP[blk*E_ + warp] = (float)cnt;
        }
    }

    // ---- conv: OT[o][t] = prompt[t] * sum_c Wc[o][c] * X[c][t] ----
    const int sm_ = warp & 3, nq_ = warp >> 2;     // m-strip (16 rows), n-quarter (64 cols)
    {
        float acc[8][4];
        #pragma unroll
        for (int i = 0; i < 8; i++)
            #pragma unroll
            for (int j = 0; j < 4; j++) acc[i][j] = 0.f;
        gemm_tiles(acc, sbase + WC_OFF, 8, sbase + XS_OFF, 32, sm_*16, nq_*64, 4, r, q);
        int m0 = sm_*16 + lane/4;
        #pragma unroll
        for (int i = 0; i < 8; i++) {
            int t = nq_*64 + 8*i + 2*(lane & 3);
            float p0 = prompts[t], p1 = prompts[t+1];
            __nv_bfloat162 lo = __float22bfloat162_rn(make_float2(acc[i][0]*p0, acc[i][1]*p1));
            __nv_bfloat162 hi = __float22bfloat162_rn(make_float2(acc[i][2]*p0, acc[i][3]*p1));
            *(unsigned*)(smem + OT_OFF + actB(m0,     t, 32)) = *(unsigned*)&lo;
            *(unsigned*)(smem + OT_OFF + actB(m0 + 8, t, 32)) = *(unsigned*)&hi;
        }
    }
    __syncthreads();

    // ---- expert loop: gemm1 (gelu+gate -> HS) then gemm2 (reg accum) ----
    float accD[8][4];
    #pragma unroll
    for (int i = 0; i < 8; i++)
        #pragma unroll
        for (int j = 0; j < 4; j++) accD[i][j] = 0.f;

    for (int e = 0; e < E_; e++) {
        if (e > 0) { __pipeline_wait_prior(1); __syncthreads(); }   // W1(e) resident

        // gemm1: H[j][t] = gelu(sum_c OT[c][t] W1[j][c] + b1[j]) * gates[e][t]
        for (int item = warp; item < 44; item += 16) {
            int ms = item >> 2, nq1 = item & 3;
            float acc[8][4];
            #pragma unroll
            for (int i = 0; i < 8; i++)
                #pragma unroll
                for (int j = 0; j < 4; j++) acc[i][j] = 0.f;
            gemm_tiles(acc, sbase + W1_OFF, 8, sbase + OT_OFF, 32, ms*16, nq1*64, 4, r, q);
            int j0 = ms*16 + lane/4, j1 = j0 + 8;
            float b1a = (j0 < HD_) ? b1[e*HD_ + j0] : 0.f;
            float b1b = (j1 < HD_) ? b1[e*HD_ + j1] : 0.f;
            #pragma unroll
            for (int i = 0; i < 8; i++) {
                int t = nq1*64 + 8*i + 2*(lane & 3);
                float g0 = gates[e*TOK + t], g1 = gates[e*TOK + t + 1];
                float v0 = gelu_t(acc[i][0] + b1a) * g0;
                float v1 = gelu_t(acc[i][1] + b1a) * g1;
                float v2 = gelu_t(acc[i][2] + b1b) * g0;
                float v3 = gelu_t(acc[i][3] + b1b) * g1;
                __nv_bfloat162 lo = __float22bfloat162_rn(make_float2(v0, v1));
                __nv_bfloat162 hi = __float22bfloat162_rn(make_float2(v2, v3));
                *(unsigned*)(smem + HS_OFF + actB(j0, t, 32)) = *(unsigned*)&lo;
                *(unsigned*)(smem + HS_OFF + actB(j1, t, 32)) = *(unsigned*)&hi;
            }
        }
        __syncthreads();                              // HS complete, W1 slot free

        if (e < E_-1) { stage_w1(smem, e+1, tid); __pipeline_commit(); __pipeline_wait_prior(1); }
        else          { __pipeline_wait_prior(0); }
        __syncthreads();                              // W2(e) resident & visible

        // gemm2: accD += W2[o][:176] * Hg[:176][t]
        gemm_tiles(accD, sbase + W2_OFF, 24, sbase + HS_OFF, 32, sm_*16, nq_*64, 11, r, q);
        __syncthreads();                              // W2 slot + HS free

        if (e < E_-1) { stage_w2(smem, e+1, tid); __pipeline_commit(); }
    }

    // ---- epilogue: out = x + y + sum_e gates*b2 ----
    {
        int o0 = sm_*16 + lane/4, o1 = o0 + 8;
        #pragma unroll
        for (int i = 0; i < 8; i++) {
            int t = nq_*64 + 8*i + 2*(lane & 3);
            float bb00 = 0.f, bb01 = 0.f, bb10 = 0.f, bb11 = 0.f;
            #pragma unroll
            for (int e = 0; e < E_; e++) {
                float ge0 = gates[e*TOK + t], ge1 = gates[e*TOK + t + 1];
                float w0 = b2[e*C_ + o0], w1v = b2[e*C_ + o1];
                bb00 += ge0 * w0;  bb01 += ge1 * w0;
                bb10 += ge0 * w1v; bb11 += ge1 * w1v;
            }
            const float* xr0 = x + xbase + (size_t)o0*HW_ + hw0 + t;
            const float* xr1 = x + xbase + (size_t)o1*HW_ + hw0 + t;
            float2 xv0 = *(const float2*)xr0;
            float2 xv1 = *(const float2*)xr1;
            float2 r0, r1;
            r0.x = xv0.x + accD[i][0] + bb00;
            r0.y = xv0.y + accD[i][1] + bb01;
            r1.x = xv1.x + accD[i][2] + bb10;
            r1.y = xv1.y + accD[i][3] + bb11;
            *(float2*)(out + xbase + (size_t)o0*HW_ + hw0 + t) = r0;
            *(float2*)(out + xbase + (size_t)o1*HW_ + hw0 + t) = r1;
        }
    }
}

// ---------------- K4: loss (parallel, deterministic) ----------------
__global__ void k_loss(float* __restrict__ out, int out_size) {
    __shared__ double imp[E_], lod[E_];
    int warp = threadIdx.x >> 5, lane = threadIdx.x & 31;
    if (warp < E_) {
        double si = 0.0, sl = 0.0;
        for (int blk = lane; blk < NBLK; blk += 32) {
            si += (double)g_impP[blk*E_ + warp];
            sl += (double)g_loadP[blk*E_ + warp];
        }
        #pragma unroll
        for (int o = 16; o; o >>= 1) {
            si += __shfl_down_sync(0xffffffffu, si, o);
            sl += __shfl_down_sync(0xffffffffu, sl, o);
        }
        if (lane == 0) { imp[warp] = si; lod[warp] = sl; }
    }
    __syncthreads();
    if (threadIdx.x == 0) {
        double mi = 0.0, ml = 0.0;
        for (int e = 0; e < E_; e++) { mi += imp[e]; ml += lod[e]; }
        mi *= 0.25; ml *= 0.25;
        double vi = 0.0, vl = 0.0;
        for (int e = 0; e < E_; e++) {
            double d = imp[e] - mi; vi += d*d;
            d = lod[e] - ml;        vl += d*d;
        }
        vi *= 0.25; vl *= 0.25;
        double loss = vi / (mi*mi + 1e-10) + vl / (ml*ml + 1e-10);
        if (out_size > NTOK*C_) out[NTOK*C_] = (float)loss;
    }
}

// ---------------- launch ----------------
extern "C" void kernel_launch(void* const* d_in, const int* in_sizes, int n_in,
                              void* d_out, int out_size) {
    (void)in_sizes; (void)n_in;
    const float* x      = (const float*)d_in[0];
    const float* sp     = (const float*)d_in[2];
    const float* w_lin  = (const float*)d_in[3];
    const float* b_lin  = (const float*)d_in[4];
    const float* w_conv = (const float*)d_in[5];
    const float* w_gate = (const float*)d_in[6];
    const float* w1     = (const float*)d_in[7];
    const float* b1     = (const float*)d_in[8];
    const float* w2     = (const float*)d_in[9];
    const float* b2     = (const float*)d_in[10];
    float* out = (float*)d_out;

    cudaFuncSetAttribute(k_main, cudaFuncAttributeMaxDynamicSharedMemorySize, SMEM_MAIN);

    int prep_total = C_*C_ + E_*HDP*C_ + E_*C_*192;
    k_prep<<<(prep_total + 255)/256, 256>>>(w_conv, w1, w2);
    k_emb<<<B_*C_, 256>>>(x);
    k_pw<<<1, 64>>>(w_lin, b_lin);
    k_main<<<NBLK, TPB, SMEM_MAIN>>>(x, sp, w_gate, b1, b2, out);
    k_loss<<<1, 128>>>(out, out_size);
}

// round 5
// speedup vs baseline: 8.2154x; 1.0048x over previous
#include <cuda_runtime.h>
#include <cuda_bf16.h>
#include <cuda_pipeline.h>

#define B_   64
#define C_   64
#define HW_  4096
#define NTOK (B_*HW_)          // 262144
#define P_   5
#define E_   4
#define HD_  170
#define JP   192               // padded hidden for fp8 k (6 * 32)
#define TOK  256
#define TPB  512
#define NBLK (NTOK/TOK)        // 1024

// ---------------- scratch (static __device__, allocation-free) ----------------
__device__ float g_emb[B_*C_];
__device__ float g_embP[NBLK*C_];          // per-(b,chunk) partial sums
__device__ float g_pw[B_*P_];
__device__ float g_impP[NBLK*E_];
__device__ float g_loadP[NBLK*E_];
__device__ uint4 g_xT4[(size_t)NTOK*64/16];     // fp8 x^T [tok][64c], 16 MB
__device__ uint4 g_gates4[(size_t)NTOK*4*4/16]; // fp32 gates [blk][4][256], 4 MB
// fp8 weights (scaled x16), packed k-pairs as u16 elements, uint4-backed
__device__ uint4 g_wcP4[32*64*2/16];        // [kp=c/2][o]        (conv B)
__device__ uint4 g_w1P4[E_*32*JP*2/16];     // [e][kp=c/2][j 192] (gemm1 B)
__device__ uint4 g_w2P4[E_*96*64*2/16];     // [e][jp=j/2][o]     (gemm2 B)

#define SW 16.0f                 // weight scale
#define SOT 128.0f               // OT scale
#define SH  4096.0f              // H scale

__device__ __forceinline__ float gelu_f(float z) {
    float u = z * (0.7978845608028654f + 0.03567740814f * z * z);
    float t;
    asm("tanh.approx.f32 %0, %1;" : "=f"(t) : "f"(u));
    return fmaf(0.5f * z, t, 0.5f * z);
}
__device__ __forceinline__ unsigned short pack_e4m3(float lo, float hi) {
    unsigned short u;
    asm("cvt.rn.satfinite.e4m3x2.f32 %0, %1, %2;" : "=h"(u) : "f"(hi), "f"(lo));
    return u;
}

// ---------------- K0: weight prep (fp32 -> scaled fp8 pairs) ----------------
__global__ void k_prep(const float* __restrict__ w_conv,
                       const float* __restrict__ w1,
                       const float* __restrict__ w2) {
    int i = blockIdx.x * blockDim.x + threadIdx.x;
    unsigned short* wc = (unsigned short*)g_wcP4;
    unsigned short* w1p = (unsigned short*)g_w1P4;
    unsigned short* w2p = (unsigned short*)g_w2P4;
    const int NWC = 32*64, NW1 = E_*32*JP, NW2 = E_*96*64;
    if (i < NWC) {
        int kp = i >> 6, o = i & 63;
        float lo = w_conv[o*C_ + 2*kp]     * SW;
        float hi = w_conv[o*C_ + 2*kp + 1] * SW;
        wc[i] = pack_e4m3(lo, hi);
    } else if (i < NWC + NW1) {
        int r = i - NWC;
        int e = r / (32*JP); int r2 = r % (32*JP);
        int kp = r2 / JP;    int j  = r2 % JP;
        float lo = (j < HD_) ? w1[((size_t)e*C_ + 2*kp    )*HD_ + j] * SW : 0.f;
        float hi = (j < HD_) ? w1[((size_t)e*C_ + 2*kp + 1)*HD_ + j] * SW : 0.f;
        w1p[r] = pack_e4m3(lo, hi);
    } else if (i < NWC + NW1 + NW2) {
        int r = i - NWC - NW1;
        int e = r / (96*64); int r2 = r % (96*64);
        int jp = r2 / 64;    int o  = r2 % 64;
        int j0 = 2*jp, j1 = 2*jp + 1;
        float lo = (j0 < HD_) ? w2[((size_t)e*HD_ + j0)*C_ + o] * SW : 0.f;
        float hi = (j1 < HD_) ? w2[((size_t)e*HD_ + j1)*C_ + o] * SW : 0.f;
        w2p[r] = pack_e4m3(lo, hi);
    }
}

// ---------------- K_xpose: x -> fp8 [tok][c] + gating + loss/emb partials ----
#define XP_TPB 256
#define XP_SMEM (64*257*4 + 4*256*4)
__global__ void __launch_bounds__(XP_TPB) k_xpose(
    const float* __restrict__ x, const float* __restrict__ w_gate)
{
    extern __shared__ char xsm[];
    float* tile = (float*)xsm;                 // [64][257]
    float* gsm  = (float*)(xsm + 64*257*4);    // [4][256]
    int tid = threadIdx.x, blk = blockIdx.x;
    int bimg = blk >> 4, hw0 = (blk & 15) * TOK;
    size_t xbase = (size_t)bimg * (C_*HW_);

    for (int i = tid; i < 64*64; i += XP_TPB) {
        int c = i >> 6, u = i & 63;
        float4 v = *(const float4*)(x + xbase + (size_t)c*HW_ + hw0 + u*4);
        float* d = &tile[c*257 + u*4];
        d[0] = v.x; d[1] = v.y; d[2] = v.z; d[3] = v.w;
    }
    for (int i = tid; i < E_*TOK; i += XP_TPB) gsm[i] = 0.f;
    __syncthreads();

    int warp = tid >> 5, lane = tid & 31;
    // emb partials: sum over 256 tokens per channel
    for (int c = warp; c < 64; c += 8) {
        float s = 0.f;
        for (int t = lane; t < TOK; t += 32) s += tile[c*257 + t];
        #pragma unroll
        for (int o = 16; o; o >>= 1) s += __shfl_xor_sync(0xffffffffu, s, o);
        if (lane == 0) g_embP[blk*64 + c] = s;
    }
    // gating (exact fp32)
    {
        int t = tid;
        float lg0 = 0.f, lg1 = 0.f, lg2 = 0.f, lg3 = 0.f;
        for (int c = 0; c < 64; c++) {
            float xv = tile[c*257 + t];
            float4 wg = *(const float4*)(w_gate + c*4);
            lg0 += xv*wg.x; lg1 += xv*wg.y; lg2 += xv*wg.z; lg3 += xv*wg.w;
        }
        float lv[4] = {lg0, lg1, lg2, lg3};
        float v1 = -1e30f, v2 = -1e30f; int i1 = 0, i2 = 0;
        #pragma unroll
        for (int e = 0; e < E_; e++) {
            if (lv[e] > v1) { v2 = v1; i2 = i1; v1 = lv[e]; i1 = e; }
            else if (lv[e] > v2) { v2 = lv[e]; i2 = e; }
        }
        float g1 = 1.0f / (1.0f + expf(v2 - v1));
        float g2 = 1.0f - g1;
        gsm[i1*TOK + t] = g1;
        gsm[i2*TOK + t] = g2;
    }
    __syncthreads();
    // gates to global
    float* gg = (float*)g_gates4;
    for (int i = tid; i < E_*TOK; i += XP_TPB) gg[(size_t)blk*1024 + i] = gsm[i];
    // loss partials
    if (warp < E_) {
        float imp = 0.f; int cnt = 0;
        for (int t = lane; t < TOK; t += 32) {
            float g = gsm[warp*TOK + t];
            imp += g; cnt += (g > 0.f);
        }
        #pragma unroll
        for (int o = 16; o; o >>= 1) {
            imp += __shfl_xor_sync(0xffffffffu, imp, o);
            cnt += __shfl_xor_sync(0xffffffffu, cnt, o);
        }
        if (lane == 0) {
            g_impP[blk*E_ + warp]  = imp;
            g_loadP[blk*E_ + warp] = (float)cnt;
        }
    }
    // transposed fp8 row for this token
    {
        int t = tid;
        unsigned rr[16];
        #pragma unroll
        for (int k = 0; k < 16; k++) {
            unsigned short a = pack_e4m3(tile[(4*k  )*257 + t], tile[(4*k+1)*257 + t]);
            unsigned short b = pack_e4m3(tile[(4*k+2)*257 + t], tile[(4*k+3)*257 + t]);
            rr[k] = (unsigned)a | ((unsigned)b << 16);
        }
        uint4* dst = g_xT4 + ((size_t)blk*TOK + t) * 4;
        dst[0] = make_uint4(rr[0],  rr[1],  rr[2],  rr[3]);
        dst[1] = make_uint4(rr[4],  rr[5],  rr[6],  rr[7]);
        dst[2] = make_uint4(rr[8],  rr[9],  rr[10], rr[11]);
        dst[3] = make_uint4(rr[12], rr[13], rr[14], rr[15]);
    }
}

// ---------------- K_emb2 + K_pw ----------------
__global__ void k_emb2() {
    int b = blockIdx.x, c = threadIdx.x;
    float s = 0.f;
    for (int ch = 0; ch < 16; ch++) s += g_embP[(b*16 + ch)*64 + c];
    g_emb[b*64 + c] = s * (1.0f / HW_);
}
__global__ void k_pw(const float* __restrict__ w_lin, const float* __restrict__ b_lin) {
    int b = threadIdx.x;
    if (b >= B_) return;
    float lg[P_];
    #pragma unroll
    for (int p = 0; p < P_; p++) lg[p] = b_lin[p];
    for (int c = 0; c < C_; c++) {
        float e = g_emb[b*C_ + c];
        #pragma unroll
        for (int p = 0; p < P_; p++) lg[p] += e * w_lin[c*P_ + p];
    }
    float mx = lg[0];
    #pragma unroll
    for (int p = 1; p < P_; p++) mx = fmaxf(mx, lg[p]);
    float s = 0.f;
    #pragma unroll
    for (int p = 0; p < P_; p++) { lg[p] = expf(lg[p] - mx); s += lg[p]; }
    float inv = 1.0f / s;
    #pragma unroll
    for (int p = 0; p < P_; p++) g_pw[b*P_ + p] = lg[p] * inv;
}

// ---------------- mma helpers ----------------
__device__ __forceinline__ void mma_f8(float* c, const unsigned* a, const unsigned* b) {
    asm volatile(
        "mma.sync.aligned.m16n8k32.row.col.f32.e4m3.e4m3.f32 "
        "{%0,%1,%2,%3},{%4,%5,%6,%7},{%8,%9},{%0,%1,%2,%3};\n"
        : "+f"(c[0]), "+f"(c[1]), "+f"(c[2]), "+f"(c[3])
        : "r"(a[0]), "r"(a[1]), "r"(a[2]), "r"(a[3]), "r"(b[0]), "r"(b[1]));
}
__device__ __forceinline__ void ldmA(unsigned* a, unsigned addr) {
    asm volatile("ldmatrix.sync.aligned.m8n8.x4.shared.b16 {%0,%1,%2,%3},[%4];\n"
        : "=r"(a[0]), "=r"(a[1]), "=r"(a[2]), "=r"(a[3]) : "r"(addr));
}
__device__ __forceinline__ void ldmBT(unsigned* b, unsigned addr) {
    asm volatile("ldmatrix.sync.aligned.m8n8.x4.trans.shared.b16 {%0,%1,%2,%3},[%4];\n"
        : "=r"(b[0]), "=r"(b[1]), "=r"(b[2]), "=r"(b[3]) : "r"(addr));
}

// ---------------- smem layout (bytes), odd 16B-unit pitches ----------------
#define XT_OFF   0          // fp8 [256 t][64c] pitch 80   (20480), overlaid by HS
#define HS_OFF   0          // fp8 [256 t][192j] pitch 208 (53248)
#define OT_OFF   53248      // fp8 [256 t][64c] pitch 80   (20480)
#define W1_OFF   73728      // u16 pairs [32 kp][192 j] pitch 400 (12800)
#define W2_OFF   86528      // u16 pairs [96 jp][64 o]  pitch 144 (13824)
#define WC_OFF   100352     // u16 pairs [32 kp][64 o]  pitch 144 (4608)
#define GT_OFF   104960     // fp32 gates [4][256]              (4096)
#define PR_OFF   109056     // fp32 prompts [256]               (1024)
#define SMEM_MAIN 110080

__device__ __forceinline__ void stage_xt(char* smem, int blk, int tid) {
    const uint4* src = g_xT4 + (size_t)blk * (TOK*4);
    for (int u = tid; u < TOK*4; u += TPB) {
        int row = u >> 2, un = u & 3;
        __pipeline_memcpy_async(smem + XT_OFF + row*80 + un*16, src + u, 16);
    }
}
__device__ __forceinline__ void stage_wc(char* smem, int tid) {
    for (int u = tid; u < 32*8; u += TPB) {
        int row = u >> 3, un = u & 7;
        __pipeline_memcpy_async(smem + WC_OFF + row*144 + un*16, g_wcP4 + u, 16);
    }
}
__device__ __forceinline__ void stage_gt(char* smem, int blk, int tid) {
    for (int u = tid; u < 256; u += TPB)
        __pipeline_memcpy_async(smem + GT_OFF + u*16, g_gates4 + (size_t)blk*256 + u, 16);
}
__device__ __forceinline__ void stage_w1(char* smem, int e, int tid) {
    for (int u = tid; u < 32*24; u += TPB) {
        int row = u / 24, un = u % 24;
        __pipeline_memcpy_async(smem + W1_OFF + row*400 + un*16, g_w1P4 + e*(32*24) + u, 16);
    }
}
__device__ __forceinline__ void stage_w2(char* smem, int e, int tid) {
    for (int u = tid; u < 96*8; u += TPB) {
        int row = u >> 3, un = u & 7;
        __pipeline_memcpy_async(smem + W2_OFF + row*144 + un*16, g_w2P4 + e*(96*8) + u, 16);
    }
}

__global__ void __launch_bounds__(TPB) k_main(
    const float* __restrict__ x,  const float* __restrict__ sp,
    const float* __restrict__ b1, const float* __restrict__ b2,
    float* __restrict__ out)
{
    extern __shared__ char smem[];
    unsigned sbase = (unsigned)__cvta_generic_to_shared(smem);
    float* gates   = (float*)(smem + GT_OFF);
    float* prompts = (float*)(smem + PR_OFF);

    const int tid  = threadIdx.x;
    const int lane = tid & 31, warp = tid >> 5;
    const int r = lane & 7, q = lane >> 3;
    const int g_ = lane >> 2, tg = lane & 3;
    const int blk  = blockIdx.x;
    const int bimg = blk >> 4;
    const int hw0  = (blk & 15) * TOK;
    const size_t xbase = (size_t)bimg * (C_*HW_);

    // ---- async prologue ----
    stage_xt(smem, blk, tid);
    stage_wc(smem, tid);
    stage_gt(smem, blk, tid);
    stage_w1(smem, 0, tid);
    __pipeline_commit();                 // G0
    stage_w2(smem, 0, tid);
    __pipeline_commit();                 // G1

    // prompts (compute while copies fly)
    if (tid < TOK) {
        float s = 0.f;
        #pragma unroll
        for (int p = 0; p < P_; p++) s += g_pw[bimg*P_ + p] * sp[p*HW_ + hw0 + tid];
        prompts[tid] = s;
    }
    __pipeline_wait_prior(1);            // G0 done (XT, Wc, gates, W1_0)
    __syncthreads();

    const int m0 = warp * 16;
    const int t0 = m0 + g_;

    // ---- conv: OT[t][o] = prompt[t] * (X @ Wc^T), fp8 out scaled x128 ----
    {
        float acc[8][4];
        #pragma unroll
        for (int i = 0; i < 8; i++)
            #pragma unroll
            for (int j = 0; j < 4; j++) acc[i][j] = 0.f;
        #pragma unroll
        for (int kk = 0; kk < 2; kk++) {
            unsigned a[4];
            ldmA(a, sbase + XT_OFF + (m0 + r + (q&1)*8)*80 + (kk*2 + (q>>1))*16);
            #pragma unroll
            for (int g4 = 0; g4 < 4; g4++) {
                unsigned bb[4];
                ldmBT(bb, sbase + WC_OFF + (kk*16 + r + (q&1)*8)*144 + (2*g4 + (q>>1))*16);
                mma_f8(acc[2*g4],     a, bb);
                mma_f8(acc[2*g4 + 1], a, bb + 2);
            }
        }
        float pr0 = prompts[t0]     * (SOT / SW);
        float pr1 = prompts[t0 + 8] * (SOT / SW);
        #pragma unroll
        for (int i = 0; i < 8; i++) {
            int oc = 8*i + 2*tg;
            *(unsigned short*)(smem + OT_OFF + t0*80 + oc)       = pack_e4m3(acc[i][0]*pr0, acc[i][1]*pr0);
            *(unsigned short*)(smem + OT_OFF + (t0+8)*80 + oc)   = pack_e4m3(acc[i][2]*pr1, acc[i][3]*pr1);
        }
    }
    __syncthreads();

    // ---- expert loop ----
    float accD[8][4];
    #pragma unroll
    for (int i = 0; i < 8; i++)
        #pragma unroll
        for (int j = 0; j < 4; j++) accD[i][j] = 0.f;

    const float INV1 = 1.0f / (SOT * SW);   // unscale gemm1 acc
    for (int e = 0; e < E_; e++) {
        if (e > 0) { __pipeline_wait_prior(1); __syncthreads(); }   // W1(e) resident

        // gemm1: H[t][j] = gelu(OT@W1 + b1) * gate * SH  (fp8)
        for (int item = warp; item < 32; item += 16) {
            int ms = item >> 1, half = item & 1;
            int mm0 = ms*16, n0 = half*96;
            float acc[12][4];
            #pragma unroll
            for (int i = 0; i < 12; i++)
                #pragma unroll
                for (int j = 0; j < 4; j++) acc[i][j] = 0.f;
            #pragma unroll
            for (int kk = 0; kk < 2; kk++) {
                unsigned a[4];
                ldmA(a, sbase + OT_OFF + (mm0 + r + (q&1)*8)*80 + (kk*2 + (q>>1))*16);
                #pragma unroll
                for (int g6 = 0; g6 < 6; g6++) {
                    unsigned bb[4];
                    ldmBT(bb, sbase + W1_OFF + (kk*16 + r + (q&1)*8)*400 + (half*12 + 2*g6 + (q>>1))*16);
                    mma_f8(acc[2*g6],     a, bb);
                    mma_f8(acc[2*g6 + 1], a, bb + 2);
                }
            }
            int tt0 = mm0 + g_;
            float ga = gates[e*TOK + tt0]     * SH;
            float gb = gates[e*TOK + tt0 + 8] * SH;
            #pragma unroll
            for (int i = 0; i < 12; i++) {
                int jj = n0 + 8*i + 2*tg;
                float b1a = (jj     < HD_) ? b1[e*HD_ + jj]     : 0.f;
                float b1b = (jj + 1 < HD_) ? b1[e*HD_ + jj + 1] : 0.f;
                float h0 = gelu_f(fmaf(acc[i][0], INV1, b1a)) * ga;
                float h1 = gelu_f(fmaf(acc[i][1], INV1, b1b)) * ga;
                float h2 = gelu_f(fmaf(acc[i][2], INV1, b1a)) * gb;
                float h3 = gelu_f(fmaf(acc[i][3], INV1, b1b)) * gb;
                *(unsigned short*)(smem + HS_OFF + tt0*208 + jj)     = pack_e4m3(h0, h1);
                *(unsigned short*)(smem + HS_OFF + (tt0+8)*208 + jj) = pack_e4m3(h2, h3);
            }
        }
        __syncthreads();                              // HS done, W1 slot free

        if (e < E_-1) { stage_w1(smem, e+1, tid); __pipeline_commit(); __pipeline_wait_prior(1); }
        else          { __pipeline_wait_prior(0); }
        __syncthreads();                              // W2(e) resident

        // gemm2: accD += H @ W2   (K = 192)
        #pragma unroll
        for (int kk = 0; kk < 6; kk++) {
            unsigned a[4];
            ldmA(a, sbase + HS_OFF + (m0 + r + (q&1)*8)*208 + (kk*2 + (q>>1))*16);
            #pragma unroll
            for (int g4 = 0; g4 < 4; g4++) {
                unsigned bb[4];
                ldmBT(bb, sbase + W2_OFF + (kk*16 + r + (q&1)*8)*144 + (2*g4 + (q>>1))*16);
                mma_f8(accD[2*g4],     a, bb);
                mma_f8(accD[2*g4 + 1], a, bb + 2);
            }
        }
        __syncthreads();                              // HS + W2 free

        if (e < E_-1) { stage_w2(smem, e+1, tid); __pipeline_commit(); }
    }

    // ---- epilogue: out = x + y + sum_e gates*b2 ----
    {
        const float INV2 = 1.0f / (SH * SW);
        float ge0[E_], ge1[E_];
        #pragma unroll
        for (int e = 0; e < E_; e++) {
            ge0[e] = gates[e*TOK + t0];
            ge1[e] = gates[e*TOK + t0 + 8];
        }
        #pragma unroll
        for (int i = 0; i < 8; i++) {
            int o0 = 8*i + 2*tg, o1 = o0 + 1;
            float b00 = 0.f, b01 = 0.f, b10 = 0.f, b11 = 0.f;
            #pragma unroll
            for (int e = 0; e < E_; e++) {
                float w0 = b2[e*C_ + o0], w1v = b2[e*C_ + o1];
                b00 += ge0[e]*w0;  b01 += ge0[e]*w1v;
                b10 += ge1[e]*w0;  b11 += ge1[e]*w1v;
            }
            size_t i00 = xbase + (size_t)o0*HW_ + hw0 + t0;
            size_t i01 = xbase + (size_t)o1*HW_ + hw0 + t0;
            out[i00]     = x[i00]     + fmaf(accD[i][0], INV2, b00);
            out[i01]     = x[i01]     + fmaf(accD[i][1], INV2, b01);
            out[i00 + 8] = x[i00 + 8] + fmaf(accD[i][2], INV2, b10);
            out[i01 + 8] = x[i01 + 8] + fmaf(accD[i][3], INV2, b11);
        }
    }
}

// ---------------- K_loss ----------------
__global__ void k_loss(float* __restrict__ out, int out_size) {
    __shared__ double imp[E_], lod[E_];
    int warp = threadIdx.x >> 5, lane = threadIdx.x & 31;
    if (warp < E_) {
        double si = 0.0, sl = 0.0;
        for (int blk = lane; blk < NBLK; blk += 32) {
            si += (double)g_impP[blk*E_ + warp];
            sl += (double)g_loadP[blk*E_ + warp];
        }
        #pragma unroll
        for (int o = 16; o; o >>= 1) {
            si += __shfl_down_sync(0xffffffffu, si, o);
            sl += __shfl_down_sync(0xffffffffu, sl, o);
        }
        if (lane == 0) { imp[warp] = si; lod[warp] = sl; }
    }
    __syncthreads();
    if (threadIdx.x == 0) {
        double mi = 0.0, ml = 0.0;
        for (int e = 0; e < E_; e++) { mi += imp[e]; ml += lod[e]; }
        mi *= 0.25; ml *= 0.25;
        double vi = 0.0, vl = 0.0;
        for (int e = 0; e < E_; e++) {
            double d = imp[e] - mi; vi += d*d;
            d = lod[e] - ml;        vl += d*d;
        }
        vi *= 0.25; vl *= 0.25;
        double loss = vi / (mi*mi + 1e-10) + vl / (ml*ml + 1e-10);
        if (out_size > NTOK*C_) out[NTOK*C_] = (float)loss;
    }
}

// ---------------- launch ----------------
extern "C" void kernel_launch(void* const* d_in, const int* in_sizes, int n_in,
                              void* d_out, int out_size) {
    (void)in_sizes; (void)n_in;
    const float* x      = (const float*)d_in[0];
    const float* sp     = (const float*)d_in[2];
    const float* w_lin  = (const float*)d_in[3];
    const float* b_lin  = (const float*)d_in[4];
    const float* w_conv = (const float*)d_in[5];
    const float* w_gate = (const float*)d_in[6];
    const float* w1     = (const float*)d_in[7];
    const float* b1     = (const float*)d_in[8];
    const float* w2     = (const float*)d_in[9];
    const float* b2     = (const float*)d_in[10];
    float* out = (float*)d_out;

    cudaFuncSetAttribute(k_main,  cudaFuncAttributeMaxDynamicSharedMemorySize, SMEM_MAIN);
    cudaFuncSetAttribute(k_xpose, cudaFuncAttributeMaxDynamicSharedMemorySize, XP_SMEM);

    int prep_total = 32*64 + E_*32*JP + E_*96*64;
    k_prep<<<(prep_total + 255)/256, 256>>>(w_conv, w1, w2);
    k_xpose<<<NBLK, XP_TPB, XP_SMEM>>>(x, w_gate);
    k_emb2<<<B_, C_>>>();
    k_pw<<<1, 64>>>(w_lin, b_lin);
    k_main<<<NBLK, TPB, SMEM_MAIN>>>(x, sp, b1, b2, out);
    k_loss<<<1, 128>>>(out, out_size);
}

// round 7
// speedup vs baseline: 8.4581x; 1.0295x over previous
#include <cuda_runtime.h>
#include <cuda_bf16.h>
#include <cuda_pipeline.h>

#define B_   64
#define C_   64
#define HW_  4096
#define NTOK (B_*HW_)          // 262144
#define P_   5
#define E_   4
#define HD_  170
#define JP   192               // padded hidden (6 * 32)
#define TOK  256
#define TPB  512
#define NBLK (NTOK/TOK)        // 1024

// ---------------- scratch (static __device__, allocation-free) ----------------
__device__ float g_emb[B_*C_];
__device__ float g_pw[B_*P_];
__device__ float g_impP[NBLK*E_];
__device__ float g_loadP[NBLK*E_];
// fp8 weights (scaled x16), packed k-pairs as u16 elements, uint4-backed
__device__ uint4 g_wcP4[32*64*2/16];        // [kp=c/2][o]        (conv B)
__device__ uint4 g_w1P4[E_*32*JP*2/16];     // [e][kp=c/2][j 192] (gemm1 B)
__device__ uint4 g_w2P4[E_*96*64*2/16];     // [e][jp=j/2][o]     (gemm2 B)

#define SW  16.0f                // weight scale
#define SOT 128.0f               // OT scale
#define SH  4096.0f              // H scale

__device__ __forceinline__ float gelu_f(float z) {
    float u = z * (0.7978845608028654f + 0.03567740814f * z * z);
    float t;
    asm("tanh.approx.f32 %0, %1;" : "=f"(t) : "f"(u));
    return fmaf(0.5f * z, t, 0.5f * z);
}
__device__ __forceinline__ unsigned pack_e4m3(float lo, float hi) {
    unsigned short u;
    asm("cvt.rn.satfinite.e4m3x2.f32 %0, %1, %2;" : "=h"(u) : "f"(hi), "f"(lo));
    return (unsigned)u;
}
__device__ __forceinline__ unsigned pack4_e4m3(float a, float b, float c, float d) {
    return pack_e4m3(a, b) | (pack_e4m3(c, d) << 16);
}

// ---------------- K0: weight prep (fp32 -> scaled fp8 pairs) ----------------
__global__ void k_prep(const float* __restrict__ w_conv,
                       const float* __restrict__ w1,
                       const float* __restrict__ w2) {
    int i = blockIdx.x * blockDim.x + threadIdx.x;
    unsigned short* wc = (unsigned short*)g_wcP4;
    unsigned short* w1p = (unsigned short*)g_w1P4;
    unsigned short* w2p = (unsigned short*)g_w2P4;
    const int NWC = 32*64, NW1 = E_*32*JP, NW2 = E_*96*64;
    if (i < NWC) {
        int kp = i >> 6, o = i & 63;
        wc[i] = (unsigned short)pack_e4m3(w_conv[o*C_ + 2*kp] * SW,
                                          w_conv[o*C_ + 2*kp + 1] * SW);
    } else if (i < NWC + NW1) {
        int r = i - NWC;
        int e = r / (32*JP); int r2 = r % (32*JP);
        int kp = r2 / JP;    int j  = r2 % JP;
        float lo = (j < HD_) ? w1[((size_t)e*C_ + 2*kp    )*HD_ + j] * SW : 0.f;
        float hi = (j < HD_) ? w1[((size_t)e*C_ + 2*kp + 1)*HD_ + j] * SW : 0.f;
        w1p[r] = (unsigned short)pack_e4m3(lo, hi);
    } else if (i < NWC + NW1 + NW2) {
        int r = i - NWC - NW1;
        int e = r / (96*64); int r2 = r % (96*64);
        int jp = r2 / 64;    int o  = r2 % 64;
        int j0 = 2*jp, j1 = 2*jp + 1;
        float lo = (j0 < HD_) ? w2[((size_t)e*HD_ + j0)*C_ + o] * SW : 0.f;
        float hi = (j1 < HD_) ? w2[((size_t)e*HD_ + j1)*C_ + o] * SW : 0.f;
        w2p[r] = (unsigned short)pack_e4m3(lo, hi);
    }
}

// ---------------- K1: emb[b,c] = mean over HW (coalesced) ----------------
__global__ void k_emb(const float* __restrict__ x) {
    int bc = blockIdx.x;
    const float4* p = (const float4*)(x + (size_t)bc * HW_);
    float s = 0.f;
    for (int i = threadIdx.x; i < HW_/4; i += blockDim.x) {
        float4 v = p[i];
        s += v.x + v.y + v.z + v.w;
    }
    #pragma unroll
    for (int o = 16; o; o >>= 1) s += __shfl_xor_sync(0xffffffffu, s, o);
    __shared__ float red[8];
    if ((threadIdx.x & 31) == 0) red[threadIdx.x >> 5] = s;
    __syncthreads();
    if (threadIdx.x == 0) {
        float t = 0.f;
        #pragma unroll
        for (int w = 0; w < 8; w++) t += red[w];
        g_emb[bc] = t * (1.0f / HW_);
    }
}

// ---------------- K2: pw[b,p] = softmax(emb @ w_lin + b_lin) ----------------
__global__ void k_pw(const float* __restrict__ w_lin, const float* __restrict__ b_lin) {
    int b = threadIdx.x;
    if (b >= B_) return;
    float lg[P_];
    #pragma unroll
    for (int p = 0; p < P_; p++) lg[p] = b_lin[p];
    for (int c = 0; c < C_; c++) {
        float e = g_emb[b*C_ + c];
        #pragma unroll
        for (int p = 0; p < P_; p++) lg[p] += e * w_lin[c*P_ + p];
    }
    float mx = lg[0];
    #pragma unroll
    for (int p = 1; p < P_; p++) mx = fmaxf(mx, lg[p]);
    float s = 0.f;
    #pragma unroll
    for (int p = 0; p < P_; p++) { lg[p] = expf(lg[p] - mx); s += lg[p]; }
    float inv = 1.0f / s;
    #pragma unroll
    for (int p = 0; p < P_; p++) g_pw[b*P_ + p] = lg[p] * inv;
}

// ---------------- mma helpers ----------------
__device__ __forceinline__ void mma_f8(float* c, const unsigned* a, const unsigned* b) {
    asm volatile(
        "mma.sync.aligned.m16n8k32.row.col.f32.e4m3.e4m3.f32 "
        "{%0,%1,%2,%3},{%4,%5,%6,%7},{%8,%9},{%0,%1,%2,%3};\n"
        : "+f"(c[0]), "+f"(c[1]), "+f"(c[2]), "+f"(c[3])
        : "r"(a[0]), "r"(a[1]), "r"(a[2]), "r"(a[3]), "r"(b[0]), "r"(b[1]));
}
__device__ __forceinline__ void ldmBT(unsigned* b, unsigned addr) {
    asm volatile("ldmatrix.sync.aligned.m8n8.x4.trans.shared.b16 {%0,%1,%2,%3},[%4];\n"
        : "=r"(b[0]), "=r"(b[1]), "=r"(b[2]), "=r"(b[3]) : "r"(addr));
}

// C-frag (8 col-groups, pg=row g_, ph=row g_+8) -> A-frags for two k32 chunks.
// aA[kc][0..3]; sel = tg>>1, srcl = 4*g_ + 2*(tg&1).
__device__ __forceinline__ void cfrag_to_afrag(
    const unsigned pg[8], const unsigned ph[8], unsigned aA[2][4], int sel, int srcl)
{
    unsigned bg[8], bh[8];
    #pragma unroll
    for (int i = 0; i < 8; i++) {
        bg[i] = (pg[i] & 0xffffu) | (__shfl_xor_sync(0xffffffffu, pg[i], 1) << 16);
        bh[i] = (ph[i] & 0xffffu) | (__shfl_xor_sync(0xffffffffu, ph[i], 1) << 16);
    }
    #pragma unroll
    for (int kc = 0; kc < 2; kc++) {
        unsigned s0g = sel ? bg[4*kc+1] : bg[4*kc];
        unsigned s0h = sel ? bh[4*kc+1] : bh[4*kc];
        unsigned s2g = sel ? bg[4*kc+3] : bg[4*kc+2];
        unsigned s2h = sel ? bh[4*kc+3] : bh[4*kc+2];
        aA[kc][0] = __shfl_sync(0xffffffffu, s0g, srcl);
        aA[kc][1] = __shfl_sync(0xffffffffu, s0h, srcl);
        aA[kc][2] = __shfl_sync(0xffffffffu, s2g, srcl);
        aA[kc][3] = __shfl_sync(0xffffffffu, s2h, srcl);
    }
}

// ---------------- smem layout (bytes) ----------------
#define TP      68              // fp32 X tile pitch (floats)
#define XT_OFF  0               // fp32 [256 tok][68] = 69632
#define W1_OFF  69632           // 4 experts * 12800 (u16 [32 kp][192 j], pitch 400B)
#define W2_OFF  120832          // 4 experts * 13824 (u16 [96 jp][64 o], pitch 144B)
#define WC_OFF  176128          // u16 [32 kp][64 o], pitch 144B = 4608
#define GT_OFF  180736          // fp32 gates [4][256] = 4096
#define PR_OFF  184832          // fp32 prompts [256] = 1024
#define LG_OFF  185856          // fp32 logit partials [512][4] = 8192
#define B1_OFF  194048          // fp32 b1s [4][192] = 3072
#define B2_OFF  197120          // fp32 b2s [4][64] = 1024
#define SMEM_MAIN 198144

__global__ void __launch_bounds__(TPB, 1) k_main(
    const float* __restrict__ x,  const float* __restrict__ sp,
    const float* __restrict__ w_gate,
    const float* __restrict__ b1, const float* __restrict__ b2,
    float* __restrict__ out)
{
    extern __shared__ char smem[];
    unsigned sbase = (unsigned)__cvta_generic_to_shared(smem);
    float* tile    = (float*)(smem + XT_OFF);
    float* gates   = (float*)(smem + GT_OFF);
    float* prompts = (float*)(smem + PR_OFF);
    float* lgp     = (float*)(smem + LG_OFF);
    float* b1s     = (float*)(smem + B1_OFF);
    float* b2s     = (float*)(smem + B2_OFF);

    const int tid  = threadIdx.x;
    const int lane = tid & 31, warp = tid >> 5;
    const int r = lane & 7, q = lane >> 3;
    const int g_ = lane >> 2, tg = lane & 3;
    const int sel  = tg >> 1;
    const int srcl = 4*g_ + 2*(tg & 1);
    const int blk  = blockIdx.x;
    const int bimg = blk >> 4;
    const int hw0  = (blk & 15) * TOK;
    const size_t xbase = (size_t)bimg * (C_*HW_);

    // ---- async weight staging: WC + all W1 + all W2 (one group) ----
    for (int u = tid; u < 32*8; u += TPB) {
        int row = u >> 3, un = u & 7;
        __pipeline_memcpy_async(smem + WC_OFF + row*144 + un*16, g_wcP4 + u, 16);
    }
    for (int u = tid; u < E_*32*24; u += TPB) {
        int e = u / (32*24), v = u % (32*24);
        int row = v / 24, un = v % 24;
        __pipeline_memcpy_async(smem + W1_OFF + e*12800 + row*400 + un*16,
                                g_w1P4 + u, 16);
    }
    for (int u = tid; u < E_*96*8; u += TPB) {
        int e = u / (96*8), v = u % (96*8);
        int row = v >> 3, un = v & 7;
        __pipeline_memcpy_async(smem + W2_OFF + e*13824 + row*144 + un*16,
                                g_w2P4 + u, 16);
    }
    __pipeline_commit();

    // ---- stage X tile transposed fp32: tile[t][c] ----
    for (int u = tid; u < 64*64; u += TPB) {
        int c = u >> 6, tu = u & 63;
        float4 v = *(const float4*)(x + xbase + (size_t)c*HW_ + hw0 + tu*4);
        int t = tu*4;
        tile[(t    )*TP + c] = v.x;
        tile[(t + 1)*TP + c] = v.y;
        tile[(t + 2)*TP + c] = v.z;
        tile[(t + 3)*TP + c] = v.w;
    }
    // prompts + biases
    if (tid < TOK) {
        float s = 0.f;
        #pragma unroll
        for (int p = 0; p < P_; p++) s += g_pw[bimg*P_ + p] * sp[p*HW_ + hw0 + tid];
        prompts[tid] = s;
    }
    for (int i = tid; i < E_*JP; i += TPB) {
        int e = i / JP, j = i % JP;
        b1s[i] = (j < HD_) ? b1[e*HD_ + j] : 0.f;
    }
    if (tid < E_*C_) b2s[tid] = b2[tid];
    __syncthreads();

    // ---- gating partials (exact fp32) ----
    {
        int t = tid & 255, h = tid >> 8;
        float lg0 = 0.f, lg1 = 0.f, lg2 = 0.f, lg3 = 0.f;
        const float* row = &tile[t*TP + h*32];
        #pragma unroll 8
        for (int c = 0; c < 32; c++) {
            float xv = row[c];
            float4 wg = *(const float4*)(w_gate + (h*32 + c)*4);
            lg0 += xv*wg.x; lg1 += xv*wg.y; lg2 += xv*wg.z; lg3 += xv*wg.w;
        }
        *(float4*)&lgp[tid*4] = make_float4(lg0, lg1, lg2, lg3);
    }
    __syncthreads();

    // ---- combine + top-2 ----
    if (tid < TOK) {
        float4 pa = *(float4*)&lgp[tid*4];
        float4 pb = *(float4*)&lgp[(256 + tid)*4];
        float lv[4] = { pa.x + pb.x, pa.y + pb.y, pa.z + pb.z, pa.w + pb.w };
        float v1 = -1e30f, v2 = -1e30f; int i1 = 0, i2 = 0;
        #pragma unroll
        for (int e = 0; e < E_; e++) {
            if (lv[e] > v1) { v2 = v1; i2 = i1; v1 = lv[e]; i1 = e; }
            else if (lv[e] > v2) { v2 = lv[e]; i2 = e; }
        }
        float g1 = 1.0f / (1.0f + expf(v2 - v1));
        float g2 = 1.0f - g1;
        float z = 0.f;
        gates[0*TOK + tid] = z; gates[1*TOK + tid] = z;
        gates[2*TOK + tid] = z; gates[3*TOK + tid] = z;
        gates[i1*TOK + tid] = g1;
        gates[i2*TOK + tid] = g2;
    }
    __pipeline_wait_prior(0);        // own async copies done
    __syncthreads();                 // everyone's copies + gates visible

    // ---- loss partials (warps 0-3) ----
    if (warp < E_) {
        float imp = 0.f; int cnt = 0;
        for (int t = lane; t < TOK; t += 32) {
            float g = gates[warp*TOK + t];
            imp += g; cnt += (g > 0.f);
        }
        #pragma unroll
        for (int o = 16; o; o >>= 1) {
            imp += __shfl_xor_sync(0xffffffffu, imp, o);
            cnt += __shfl_xor_sync(0xffffffffu, cnt, o);
        }
        if (lane == 0) {
            g_impP[blk*E_ + warp]  = imp;
            g_loadP[blk*E_ + warp] = (float)cnt;
        }
    }

    const int m0 = warp * 16;        // warp's 16 tokens
    const int ta = m0 + g_;          // row g_
    const int tb = ta + 8;           // row g_+8

    // ---- conv: build X A-frags from fp32 tile, mma, shuffle into OT A-frags ----
    unsigned otA[2][4];
    {
        unsigned xA[2][4];
        #pragma unroll
        for (int kc = 0; kc < 2; kc++) {
            float4 f0 = *(float4*)&tile[ta*TP + kc*32 + 4*tg];
            float4 f1 = *(float4*)&tile[tb*TP + kc*32 + 4*tg];
            float4 f2 = *(float4*)&tile[ta*TP + kc*32 + 16 + 4*tg];
            float4 f3 = *(float4*)&tile[tb*TP + kc*32 + 16 + 4*tg];
            xA[kc][0] = pack4_e4m3(f0.x, f0.y, f0.z, f0.w);
            xA[kc][1] = pack4_e4m3(f1.x, f1.y, f1.z, f1.w);
            xA[kc][2] = pack4_e4m3(f2.x, f2.y, f2.z, f2.w);
            xA[kc][3] = pack4_e4m3(f3.x, f3.y, f3.z, f3.w);
        }
        float acc[8][4];
        #pragma unroll
        for (int i = 0; i < 8; i++)
            #pragma unroll
            for (int j = 0; j < 4; j++) acc[i][j] = 0.f;
        #pragma unroll
        for (int kc = 0; kc < 2; kc++)
            #pragma unroll
            for (int g4 = 0; g4 < 4; g4++) {
                unsigned bb[4];
                ldmBT(bb, sbase + WC_OFF + (kc*16 + r + (q&1)*8)*144 + (2*g4 + (q>>1))*16);
                mma_f8(acc[2*g4],     xA[kc], bb);
                mma_f8(acc[2*g4 + 1], xA[kc], bb + 2);
            }
        float pr0 = prompts[ta] * (SOT / SW);
        float pr1 = prompts[tb] * (SOT / SW);
        unsigned pg[8], ph[8];
        #pragma unroll
        for (int i = 0; i < 8; i++) {
            pg[i] = pack_e4m3(acc[i][0]*pr0, acc[i][1]*pr0);
            ph[i] = pack_e4m3(acc[i][2]*pr1, acc[i][3]*pr1);
        }
        cfrag_to_afrag(pg, ph, otA, sel, srcl);
    }

    // ---- expert loop: fully register-resident, no block syncs ----
    float accD[8][4];
    #pragma unroll
    for (int i = 0; i < 8; i++)
        #pragma unroll
        for (int j = 0; j < 4; j++) accD[i][j] = 0.f;

    const float INV1 = 1.0f / (SOT * SW);
    float ge0[E_], ge1[E_];
    #pragma unroll
    for (int e = 0; e < E_; e++) {
        ge0[e] = gates[e*TOK + ta];
        ge1[e] = gates[e*TOK + tb];
    }

    #pragma unroll
    for (int e = 0; e < E_; e++) {
        const unsigned w1b = sbase + W1_OFF + e*12800;
        const unsigned w2b = sbase + W2_OFF + e*13824;
        float ga = ge0[e] * SH, gb = ge1[e] * SH;
        #pragma unroll
        for (int s = 0; s < 3; s++) {            // 64-j slices
            float acc1[8][4];
            #pragma unroll
            for (int i = 0; i < 8; i++)
                #pragma unroll
                for (int j = 0; j < 4; j++) acc1[i][j] = 0.f;
            #pragma unroll
            for (int kc = 0; kc < 2; kc++)
                #pragma unroll
                for (int g4 = 0; g4 < 4; g4++) {
                    unsigned bb[4];
                    ldmBT(bb, w1b + (kc*16 + r + (q&1)*8)*400 + (8*s + 2*g4 + (q>>1))*16);
                    mma_f8(acc1[2*g4],     otA[kc], bb);
                    mma_f8(acc1[2*g4 + 1], otA[kc], bb + 2);
                }
            // activation epilogue -> fp8 pairs
            unsigned pg[8], ph[8];
            #pragma unroll
            for (int i = 0; i < 8; i++) {
                int j0 = s*64 + 8*i + 2*tg;
                float bva = b1s[e*JP + j0];
                float bvb = b1s[e*JP + j0 + 1];
                float v0 = gelu_f(fmaf(acc1[i][0], INV1, bva)) * ga;
                float v1 = gelu_f(fmaf(acc1[i][1], INV1, bvb)) * ga;
                float v2 = gelu_f(fmaf(acc1[i][2], INV1, bva)) * gb;
                float v3 = gelu_f(fmaf(acc1[i][3], INV1, bvb)) * gb;
                pg[i] = pack_e4m3(v0, v1);
                ph[i] = pack_e4m3(v2, v3);
            }
            unsigned aH[2][4];
            cfrag_to_afrag(pg, ph, aH, sel, srcl);
            // gemm2 partial over this slice's two k32 chunks
            #pragma unroll
            for (int kc = 0; kc < 2; kc++) {
                int kk = 2*s + kc;
                #pragma unroll
                for (int g4 = 0; g4 < 4; g4++) {
                    unsigned bb[4];
                    ldmBT(bb, w2b + (kk*16 + r + (q&1)*8)*144 + (2*g4 + (q>>1))*16);
                    mma_f8(accD[2*g4],     aH[kc], bb);
                    mma_f8(accD[2*g4 + 1], aH[kc], bb + 2);
                }
            }
        }
    }

    // ---- epilogue: out = x + y + sum_e gates*b2 ----
    {
        const float INV2 = 1.0f / (SH * SW);
        #pragma unroll
        for (int i = 0; i < 8; i++) {
            int o0 = 8*i + 2*tg, o1 = o0 + 1;
            float b00 = 0.f, b01 = 0.f, b10 = 0.f, b11 = 0.f;
            #pragma unroll
            for (int e = 0; e < E_; e++) {
                float w0 = b2s[e*C_ + o0], w1v = b2s[e*C_ + o1];
                b00 += ge0[e]*w0;  b01 += ge0[e]*w1v;
                b10 += ge1[e]*w0;  b11 += ge1[e]*w1v;
            }
            float x00 = tile[ta*TP + o0], x01 = tile[ta*TP + o1];
            float x10 = tile[tb*TP + o0], x11 = tile[tb*TP + o1];
            size_t p0 = xbase + (size_t)o0*HW_ + hw0;
            size_t p1 = xbase + (size_t)o1*HW_ + hw0;
            out[p0 + ta] = x00 + fmaf(accD[i][0], INV2, b00);
            out[p1 + ta] = x01 + fmaf(accD[i][1], INV2, b01);
            out[p0 + tb] = x10 + fmaf(accD[i][2], INV2, b10);
            out[p1 + tb] = x11 + fmaf(accD[i][3], INV2, b11);
        }
    }
}

// ---------------- K_loss ----------------
__global__ void k_loss(float* __restrict__ out, int out_size) {
    __shared__ double imp[E_], lod[E_];
    int warp = threadIdx.x >> 5, lane = threadIdx.x & 31;
    if (warp < E_) {
        double si = 0.0, sl = 0.0;
        for (int blk = lane; blk < NBLK; blk += 32) {
            si += (double)g_impP[blk*E_ + warp];
            sl += (double)g_loadP[blk*E_ + warp];
        }
        #pragma unroll
        for (int o = 16; o; o >>= 1) {
            si += __shfl_down_sync(0xffffffffu, si, o);
            sl += __shfl_down_sync(0xffffffffu, sl, o);
        }
        if (lane == 0) { imp[warp] = si; lod[warp] = sl; }
    }
    __syncthreads();
    if (threadIdx.x == 0) {
        double mi = 0.0, ml = 0.0;
        for (int e = 0; e < E_; e++) { mi += imp[e]; ml += lod[e]; }
        mi *= 0.25; ml *= 0.25;
        double vi = 0.0, vl = 0.0;
        for (int e = 0; e < E_; e++) {
            double d = imp[e] - mi; vi += d*d;
            d = lod[e] - ml;        vl += d*d;
        }
        vi *= 0.25; vl *= 0.25;
        double loss = vi / (mi*mi + 1e-10) + vl / (ml*ml + 1e-10);
        if (out_size > NTOK*C_) out[NTOK*C_] = (float)loss;
    }
}

// ---------------- launch ----------------
extern "C" void kernel_launch(void* const* d_in, const int* in_sizes, int n_in,
                              void* d_out, int out_size) {
    (void)in_sizes; (void)n_in;
    const float* x      = (const float*)d_in[0];
    const float* sp     = (const float*)d_in[2];
    const float* w_lin  = (const float*)d_in[3];
    const float* b_lin  = (const float*)d_in[4];
    const float* w_conv = (const float*)d_in[5];
    const float* w_gate = (const float*)d_in[6];
    const float* w1     = (const float*)d_in[7];
    const float* b1     = (const float*)d_in[8];
    const float* w2     = (const float*)d_in[9];
    const float* b2     = (const float*)d_in[10];
    float* out = (float*)d_out;

    cudaFuncSetAttribute(k_main, cudaFuncAttributeMaxDynamicSharedMemorySize, SMEM_MAIN);

    int prep_total = 32*64 + E_*32*JP + E_*96*64;
    k_prep<<<(prep_total + 255)/256, 256>>>(w_conv, w1, w2);
    k_emb<<<B_*C_, 256>>>(x);
    k_pw<<<1, 64>>>(w_lin, b_lin);
    k_main<<<NBLK, TPB, SMEM_MAIN>>>(x, sp, w_gate, b1, b2, out);
    k_loss<<<1, 128>>>(out, out_size);
}

// round 8
// speedup vs baseline: 9.4939x; 1.1225x over previous
#include <cuda_runtime.h>
#include <cuda_bf16.h>
#include <cuda_pipeline.h>

#define B_   64
#define C_   64
#define HW_  4096
#define NTOK (B_*HW_)          // 262144
#define P_   5
#define E_   4
#define HD_  170
#define JP   192               // padded hidden (6 * 32)
#define TOK  256
#define TPB  512
#define NBLK (NTOK/TOK)        // 1024
#define GRID_MAIN 148

// ---------------- scratch (static __device__, allocation-free) ----------------
__device__ float g_emb[B_*C_];
__device__ float g_pw[B_*P_];
__device__ float g_impP[NBLK*E_];
__device__ float g_loadP[NBLK*E_];
__device__ uint4 g_xT4[(size_t)NTOK*64/16];     // fp8 x^T [tok][64c], 16 MB
__device__ uint4 g_gp4[(size_t)NBLK*1280/4];    // fp32 [tile][gates 4*256 | prompts 256]
// fp8 weights (scaled x16), packed k-pairs as u16 elements
__device__ uint4 g_wcP4[32*64*2/16];        // [kp=c/2][o]        (conv B)
__device__ uint4 g_w1P4[E_*32*JP*2/16];     // [e][kp=c/2][j 192] (gemm1 B)
__device__ uint4 g_w2P4[E_*96*64*2/16];     // [e][jp=j/2][o]     (gemm2 B)

#define SW  16.0f                // weight scale
#define SOT 128.0f               // OT scale
#define SH  4096.0f              // H scale

__device__ __forceinline__ float gelu_f(float z) {
    float u = z * (0.7978845608028654f + 0.03567740814f * z * z);
    float t;
    asm("tanh.approx.f32 %0, %1;" : "=f"(t) : "f"(u));
    return fmaf(0.5f * z, t, 0.5f * z);
}
__device__ __forceinline__ unsigned pack_e4m3(float lo, float hi) {
    unsigned short u;
    asm("cvt.rn.satfinite.e4m3x2.f32 %0, %1, %2;" : "=h"(u) : "f"(hi), "f"(lo));
    return (unsigned)u;
}
__device__ __forceinline__ unsigned pack4_e4m3(float a, float b, float c, float d) {
    return pack_e4m3(a, b) | (pack_e4m3(c, d) << 16);
}

// ---------------- K0: weight prep (fp32 -> scaled fp8 pairs) ----------------
__global__ void k_prep(const float* __restrict__ w_conv,
                       const float* __restrict__ w1,
                       const float* __restrict__ w2) {
    int i = blockIdx.x * blockDim.x + threadIdx.x;
    unsigned short* wc = (unsigned short*)g_wcP4;
    unsigned short* w1p = (unsigned short*)g_w1P4;
    unsigned short* w2p = (unsigned short*)g_w2P4;
    const int NWC = 32*64, NW1 = E_*32*JP, NW2 = E_*96*64;
    if (i < NWC) {
        int kp = i >> 6, o = i & 63;
        wc[i] = (unsigned short)pack_e4m3(w_conv[o*C_ + 2*kp] * SW,
                                          w_conv[o*C_ + 2*kp + 1] * SW);
    } else if (i < NWC + NW1) {
        int r = i - NWC;
        int e = r / (32*JP); int r2 = r % (32*JP);
        int kp = r2 / JP;    int j  = r2 % JP;
        float lo = (j < HD_) ? w1[((size_t)e*C_ + 2*kp    )*HD_ + j] * SW : 0.f;
        float hi = (j < HD_) ? w1[((size_t)e*C_ + 2*kp + 1)*HD_ + j] * SW : 0.f;
        w1p[r] = (unsigned short)pack_e4m3(lo, hi);
    } else if (i < NWC + NW1 + NW2) {
        int r = i - NWC - NW1;
        int e = r / (96*64); int r2 = r % (96*64);
        int jp = r2 / 64;    int o  = r2 % 64;
        int j0 = 2*jp, j1 = 2*jp + 1;
        float lo = (j0 < HD_) ? w2[((size_t)e*HD_ + j0)*C_ + o] * SW : 0.f;
        float hi = (j1 < HD_) ? w2[((size_t)e*HD_ + j1)*C_ + o] * SW : 0.f;
        w2p[r] = (unsigned short)pack_e4m3(lo, hi);
    }
}

// ---------------- K1: emb[b,c] = mean over HW ----------------
__global__ void k_emb(const float* __restrict__ x) {
    int bc = blockIdx.x;
    const float4* p = (const float4*)(x + (size_t)bc * HW_);
    float s = 0.f;
    for (int i = threadIdx.x; i < HW_/4; i += blockDim.x) {
        float4 v = p[i];
        s += v.x + v.y + v.z + v.w;
    }
    #pragma unroll
    for (int o = 16; o; o >>= 1) s += __shfl_xor_sync(0xffffffffu, s, o);
    __shared__ float red[8];
    if ((threadIdx.x & 31) == 0) red[threadIdx.x >> 5] = s;
    __syncthreads();
    if (threadIdx.x == 0) {
        float t = 0.f;
        #pragma unroll
        for (int w = 0; w < 8; w++) t += red[w];
        g_emb[bc] = t * (1.0f / HW_);
    }
}

// ---------------- K2: pw[b,p] = softmax(emb @ w_lin + b_lin), block per b ----
__global__ void k_pw(const float* __restrict__ w_lin, const float* __restrict__ b_lin) {
    int b = blockIdx.x, c = threadIdx.x;   // 64 threads
    __shared__ float red[2][P_];
    float e = g_emb[b*C_ + c];
    float lg[P_];
    #pragma unroll
    for (int p = 0; p < P_; p++) lg[p] = e * w_lin[c*P_ + p];
    #pragma unroll
    for (int o = 16; o; o >>= 1)
        #pragma unroll
        for (int p = 0; p < P_; p++) lg[p] += __shfl_xor_sync(0xffffffffu, lg[p], o);
    if ((c & 31) == 0)
        #pragma unroll
        for (int p = 0; p < P_; p++) red[c >> 5][p] = lg[p];
    __syncthreads();
    if (c == 0) {
        float v[P_];
        #pragma unroll
        for (int p = 0; p < P_; p++) v[p] = red[0][p] + red[1][p] + b_lin[p];
        float mx = v[0];
        #pragma unroll
        for (int p = 1; p < P_; p++) mx = fmaxf(mx, v[p]);
        float s = 0.f;
        #pragma unroll
        for (int p = 0; p < P_; p++) { v[p] = expf(v[p] - mx); s += v[p]; }
        float inv = 1.0f / s;
        #pragma unroll
        for (int p = 0; p < P_; p++) g_pw[b*P_ + p] = v[p] * inv;
    }
}

// ---------------- K_gate: exact gating + prompts + loss partials + fp8 x^T ----
#define GA_TPB 256
__global__ void __launch_bounds__(GA_TPB) k_gate(
    const float* __restrict__ x, const float* __restrict__ sp,
    const float* __restrict__ w_gate)
{
    __shared__ float gsm[E_*TOK];
    const int t = threadIdx.x, tile = blockIdx.x;
    const int bimg = tile >> 4, hw0 = (tile & 15) * TOK;
    const size_t xbase = (size_t)bimg * (C_*HW_);

    float l0 = 0.f, l1 = 0.f, l2 = 0.f, l3 = 0.f;
    unsigned xr[16];
    const float* xp = x + xbase + hw0 + t;
    #pragma unroll
    for (int cq = 0; cq < 16; cq++) {
        float v0 = xp[(size_t)(4*cq    )*HW_];
        float v1 = xp[(size_t)(4*cq + 1)*HW_];
        float v2 = xp[(size_t)(4*cq + 2)*HW_];
        float v3 = xp[(size_t)(4*cq + 3)*HW_];
        #pragma unroll
        for (int k = 0; k < 4; k++) {
            float vv = (k == 0) ? v0 : (k == 1) ? v1 : (k == 2) ? v2 : v3;
            float4 wg = *(const float4*)(w_gate + (4*cq + k)*4);
            l0 += vv*wg.x; l1 += vv*wg.y; l2 += vv*wg.z; l3 += vv*wg.w;
        }
        xr[cq] = pack4_e4m3(v0, v1, v2, v3);
    }
    // fp8 transposed row out
    {
        uint4* dst = g_xT4 + ((size_t)tile*TOK + t) * 4;
        dst[0] = make_uint4(xr[0],  xr[1],  xr[2],  xr[3]);
        dst[1] = make_uint4(xr[4],  xr[5],  xr[6],  xr[7]);
        dst[2] = make_uint4(xr[8],  xr[9],  xr[10], xr[11]);
        dst[3] = make_uint4(xr[12], xr[13], xr[14], xr[15]);
    }
    // top-2
    float lv[4] = { l0, l1, l2, l3 };
    float v1m = -1e30f, v2m = -1e30f; int i1 = 0, i2 = 0;
    #pragma unroll
    for (int e = 0; e < E_; e++) {
        if (lv[e] > v1m) { v2m = v1m; i2 = i1; v1m = lv[e]; i1 = e; }
        else if (lv[e] > v2m) { v2m = lv[e]; i2 = e; }
    }
    float g1 = 1.0f / (1.0f + expf(v2m - v1m));
    float g2 = 1.0f - g1;
    #pragma unroll
    for (int e = 0; e < E_; e++)
        gsm[e*TOK + t] = (e == i1) ? g1 : ((e == i2) ? g2 : 0.f);
    // prompt
    float pr = 0.f;
    #pragma unroll
    for (int p = 0; p < P_; p++) pr += g_pw[bimg*P_ + p] * sp[p*HW_ + hw0 + t];
    __syncthreads();
    // write gates + prompt to global
    float* gpf = (float*)g_gp4 + (size_t)tile*1280;
    #pragma unroll
    for (int i = 0; i < 4; i++) gpf[i*TOK + t] = gsm[i*TOK + t];
    gpf[1024 + t] = pr;
    // loss partials
    int warp = t >> 5, lane = t & 31;
    if (warp < E_) {
        float imp = 0.f; int cnt = 0;
        for (int u = lane; u < TOK; u += 32) {
            float g = gsm[warp*TOK + u];
            imp += g; cnt += (g > 0.f);
        }
        #pragma unroll
        for (int o = 16; o; o >>= 1) {
            imp += __shfl_xor_sync(0xffffffffu, imp, o);
            cnt += __shfl_xor_sync(0xffffffffu, cnt, o);
        }
        if (lane == 0) {
            g_impP[tile*E_ + warp]  = imp;
            g_loadP[tile*E_ + warp] = (float)cnt;
        }
    }
}

// ---------------- mma helpers ----------------
__device__ __forceinline__ void mma_f8(float* c, const unsigned* a, const unsigned* b) {
    asm volatile(
        "mma.sync.aligned.m16n8k32.row.col.f32.e4m3.e4m3.f32 "
        "{%0,%1,%2,%3},{%4,%5,%6,%7},{%8,%9},{%0,%1,%2,%3};\n"
        : "+f"(c[0]), "+f"(c[1]), "+f"(c[2]), "+f"(c[3])
        : "r"(a[0]), "r"(a[1]), "r"(a[2]), "r"(a[3]), "r"(b[0]), "r"(b[1]));
}
__device__ __forceinline__ void ldmA(unsigned* a, unsigned addr) {
    asm volatile("ldmatrix.sync.aligned.m8n8.x4.shared.b16 {%0,%1,%2,%3},[%4];\n"
        : "=r"(a[0]), "=r"(a[1]), "=r"(a[2]), "=r"(a[3]) : "r"(addr));
}
__device__ __forceinline__ void ldmBT(unsigned* b, unsigned addr) {
    asm volatile("ldmatrix.sync.aligned.m8n8.x4.trans.shared.b16 {%0,%1,%2,%3},[%4];\n"
        : "=r"(b[0]), "=r"(b[1]), "=r"(b[2]), "=r"(b[3]) : "r"(addr));
}

// C-frag (8 col-groups, pg=row g_, ph=row g_+8) -> A-frags for two k32 chunks.
__device__ __forceinline__ void cfrag_to_afrag(
    const unsigned pg[8], const unsigned ph[8], unsigned aA[2][4], int sel, int srcl)
{
    unsigned bg[8], bh[8];
    #pragma unroll
    for (int i = 0; i < 8; i++) {
        bg[i] = (pg[i] & 0xffffu) | (__shfl_xor_sync(0xffffffffu, pg[i], 1) << 16);
        bh[i] = (ph[i] & 0xffffu) | (__shfl_xor_sync(0xffffffffu, ph[i], 1) << 16);
    }
    #pragma unroll
    for (int kc = 0; kc < 2; kc++) {
        unsigned s0g = sel ? bg[4*kc+1] : bg[4*kc];
        unsigned s0h = sel ? bh[4*kc+1] : bh[4*kc];
        unsigned s2g = sel ? bg[4*kc+3] : bg[4*kc+2];
        unsigned s2h = sel ? bh[4*kc+3] : bh[4*kc+2];
        aA[kc][0] = __shfl_sync(0xffffffffu, s0g, srcl);
        aA[kc][1] = __shfl_sync(0xffffffffu, s0h, srcl);
        aA[kc][2] = __shfl_sync(0xffffffffu, s2g, srcl);
        aA[kc][3] = __shfl_sync(0xffffffffu, s2h, srcl);
    }
}

// ---------------- k_main smem layout (bytes) ----------------
#define XT_OFF  0               // 2 x (256 rows * 80B) = 40960
#define GP_OFF  40960           // 2 x 5120 (gates 4096 + prompts 1024)
#define W1_OFF  51200           // 4 x 12800 (u16 [32 kp][192 j], pitch 400B)
#define W2_OFF  102400          // 4 x 13824 (u16 [96 jp][64 o], pitch 144B)
#define WC_OFF  157696          // u16 [32 kp][64 o], pitch 144B = 4608
#define B1_OFF  162304          // fp32 [4][192] = 3072
#define B2_OFF  165376          // fp32 [4][64] = 1024
#define SMEM_MAIN 166400

__device__ __forceinline__ void stage_tile(char* smem, int buf, int tile, int tid) {
    const uint4* src = g_xT4 + (size_t)tile * (TOK*4);
    for (int u = tid; u < TOK*4; u += TPB) {
        int row = u >> 2, un = u & 3;
        __pipeline_memcpy_async(smem + XT_OFF + buf*20480 + row*80 + un*16, src + u, 16);
    }
    const uint4* gsrc = g_gp4 + (size_t)tile * 320;
    for (int u = tid; u < 320; u += TPB)
        __pipeline_memcpy_async(smem + GP_OFF + buf*5120 + u*16, gsrc + u, 16);
}

__global__ void __launch_bounds__(TPB, 1) k_main(
    const float* __restrict__ x,
    const float* __restrict__ b1, const float* __restrict__ b2,
    float* __restrict__ out)
{
    extern __shared__ char smem[];
    unsigned sbase = (unsigned)__cvta_generic_to_shared(smem);
    float* b1s = (float*)(smem + B1_OFF);
    float* b2s = (float*)(smem + B2_OFF);

    const int tid  = threadIdx.x;
    const int lane = tid & 31, warp = tid >> 5;
    const int r = lane & 7, q = lane >> 3;
    const int g_ = lane >> 2, tg = lane & 3;
    const int sel  = tg >> 1;
    const int srcl = 4*g_ + 2*(tg & 1);
    const int m0 = warp * 16, ta = m0 + g_, tb = ta + 8;

    // ---- one-time staging: all weights + first tile ----
    for (int u = tid; u < 32*8; u += TPB) {
        int row = u >> 3, un = u & 7;
        __pipeline_memcpy_async(smem + WC_OFF + row*144 + un*16, g_wcP4 + u, 16);
    }
    for (int u = tid; u < E_*32*24; u += TPB) {
        int e = u / (32*24), v = u % (32*24);
        int row = v / 24, un = v % 24;
        __pipeline_memcpy_async(smem + W1_OFF + e*12800 + row*400 + un*16, g_w1P4 + u, 16);
    }
    for (int u = tid; u < E_*96*8; u += TPB) {
        int e = u / (96*8), v = u % (96*8);
        int row = v >> 3, un = v & 7;
        __pipeline_memcpy_async(smem + W2_OFF + e*13824 + row*144 + un*16, g_w2P4 + u, 16);
    }
    stage_tile(smem, 0, blockIdx.x, tid);
    __pipeline_commit();
    for (int i = tid; i < E_*JP; i += TPB) {
        int e = i / JP, j = i % JP;
        b1s[i] = (j < HD_) ? b1[e*HD_ + j] : 0.f;
    }
    if (tid < E_*C_) b2s[tid] = b2[tid];
    __pipeline_wait_prior(0);
    __syncthreads();

    const float INV1 = 1.0f / (SOT * SW);
    const float INV2 = 1.0f / (SH * SW);

    int buf = 0;
    for (int tile = blockIdx.x; tile < NBLK; tile += GRID_MAIN) {
        const int bimg = tile >> 4;
        const int hw0  = (tile & 15) * TOK;
        const size_t xbase = (size_t)bimg * (C_*HW_);
        const float* gtp = (float*)(smem + GP_OFF + buf*5120);

        float ge0[E_], ge1[E_];
        #pragma unroll
        for (int e = 0; e < E_; e++) {
            ge0[e] = gtp[e*TOK + ta];
            ge1[e] = gtp[e*TOK + tb];
        }
        float pr0 = gtp[1024 + ta] * (SOT / SW);
        float pr1 = gtp[1024 + tb] * (SOT / SW);

        // ---- conv: A-frags via ldmatrix from fp8 XT tile ----
        unsigned otA[2][4];
        {
            unsigned xA[2][4];
            #pragma unroll
            for (int kc = 0; kc < 2; kc++)
                ldmA(xA[kc], sbase + XT_OFF + buf*20480 + (m0 + r + (q&1)*8)*80 + (kc*2 + (q>>1))*16);
            float acc[8][4];
            #pragma unroll
            for (int i = 0; i < 8; i++)
                #pragma unroll
                for (int j = 0; j < 4; j++) acc[i][j] = 0.f;
            #pragma unroll
            for (int kc = 0; kc < 2; kc++)
                #pragma unroll
                for (int g4 = 0; g4 < 4; g4++) {
                    unsigned bb[4];
                    ldmBT(bb, sbase + WC_OFF + (kc*16 + r + (q&1)*8)*144 + (2*g4 + (q>>1))*16);
                    mma_f8(acc[2*g4],     xA[kc], bb);
                    mma_f8(acc[2*g4 + 1], xA[kc], bb + 2);
                }
            unsigned pg[8], ph[8];
            #pragma unroll
            for (int i = 0; i < 8; i++) {
                pg[i] = pack_e4m3(acc[i][0]*pr0, acc[i][1]*pr0);
                ph[i] = pack_e4m3(acc[i][2]*pr1, acc[i][3]*pr1);
            }
            cfrag_to_afrag(pg, ph, otA, sel, srcl);
        }

        // ---- prefetch next tile while experts run ----
        int nt = tile + GRID_MAIN;
        if (nt < NBLK) stage_tile(smem, buf ^ 1, nt, tid);
        __pipeline_commit();

        // ---- expert loop: register-resident ----
        float accD[8][4];
        #pragma unroll
        for (int i = 0; i < 8; i++)
            #pragma unroll
            for (int j = 0; j < 4; j++) accD[i][j] = 0.f;

        #pragma unroll
        for (int e = 0; e < E_; e++) {
            const unsigned w1b = sbase + W1_OFF + e*12800;
            const unsigned w2b = sbase + W2_OFF + e*13824;
            float ga = ge0[e] * SH, gb = ge1[e] * SH;
            #pragma unroll
            for (int s = 0; s < 3; s++) {
                float acc1[8][4];
                #pragma unroll
                for (int i = 0; i < 8; i++)
                    #pragma unroll
                    for (int j = 0; j < 4; j++) acc1[i][j] = 0.f;
                #pragma unroll
                for (int kc = 0; kc < 2; kc++)
                    #pragma unroll
                    for (int g4 = 0; g4 < 4; g4++) {
                        unsigned bb[4];
                        ldmBT(bb, w1b + (kc*16 + r + (q&1)*8)*400 + (8*s + 2*g4 + (q>>1))*16);
                        mma_f8(acc1[2*g4],     otA[kc], bb);
                        mma_f8(acc1[2*g4 + 1], otA[kc], bb + 2);
                    }
                unsigned pg[8], ph[8];
                #pragma unroll
                for (int i = 0; i < 8; i++) {
                    int j0 = s*64 + 8*i + 2*tg;
                    float bva = b1s[e*JP + j0];
                    float bvb = b1s[e*JP + j0 + 1];
                    float v0 = gelu_f(fmaf(acc1[i][0], INV1, bva)) * ga;
                    float v1 = gelu_f(fmaf(acc1[i][1], INV1, bvb)) * ga;
                    float v2 = gelu_f(fmaf(acc1[i][2], INV1, bva)) * gb;
                    float v3 = gelu_f(fmaf(acc1[i][3], INV1, bvb)) * gb;
                    pg[i] = pack_e4m3(v0, v1);
                    ph[i] = pack_e4m3(v2, v3);
                }
                unsigned aH[2][4];
                cfrag_to_afrag(pg, ph, aH, sel, srcl);
                #pragma unroll
                for (int kc = 0; kc < 2; kc++) {
                    int kk = 2*s + kc;
                    #pragma unroll
                    for (int g4 = 0; g4 < 4; g4++) {
                        unsigned bb[4];
                        ldmBT(bb, w2b + (kk*16 + r + (q&1)*8)*144 + (2*g4 + (q>>1))*16);
                        mma_f8(accD[2*g4],     aH[kc], bb);
                        mma_f8(accD[2*g4 + 1], aH[kc], bb + 2);
                    }
                }
            }
        }

        // ---- epilogue: out = x + y + sum_e gates*b2 (residual from L2) ----
        #pragma unroll
        for (int i = 0; i < 8; i++) {
            int o0 = 8*i + 2*tg, o1 = o0 + 1;
            float b00 = 0.f, b01 = 0.f, b10 = 0.f, b11 = 0.f;
            #pragma unroll
            for (int e = 0; e < E_; e++) {
                float w0 = b2s[e*C_ + o0], w1v = b2s[e*C_ + o1];
                b00 += ge0[e]*w0;  b01 += ge0[e]*w1v;
                b10 += ge1[e]*w0;  b11 += ge1[e]*w1v;
            }
            size_t p0 = xbase + (size_t)o0*HW_ + hw0;
            size_t p1 = xbase + (size_t)o1*HW_ + hw0;
            out[p0 + ta] = x[p0 + ta] + fmaf(accD[i][0], INV2, b00);
            out[p1 + ta] = x[p1 + ta] + fmaf(accD[i][1], INV2, b01);
            out[p0 + tb] = x[p0 + tb] + fmaf(accD[i][2], INV2, b10);
            out[p1 + tb] = x[p1 + tb] + fmaf(accD[i][3], INV2, b11);
        }

        __pipeline_wait_prior(0);
        __syncthreads();
        buf ^= 1;
    }
}

// ---------------- K_loss ----------------
__global__ void k_loss(float* __restrict__ out, int out_size) {
    __shared__ double imp[E_], lod[E_];
    int warp = threadIdx.x >> 5, lane = threadIdx.x & 31;
    if (warp < E_) {
        double si = 0.0, sl = 0.0;
        for (int blk = lane; blk < NBLK; blk += 32) {
            si += (double)g_impP[blk*E_ + warp];
            sl += (double)g_loadP[blk*E_ + warp];
        }
        #pragma unroll
        for (int o = 16; o; o >>= 1) {
            si += __shfl_down_sync(0xffffffffu, si, o);
            sl += __shfl_down_sync(0xffffffffu, sl, o);
        }
        if (lane == 0) { imp[warp] = si; lod[warp] = sl; }
    }
    __syncthreads();
    if (threadIdx.x == 0) {
        double mi = 0.0, ml = 0.0;
        for (int e = 0; e < E_; e++) { mi += imp[e]; ml += lod[e]; }
        mi *= 0.25; ml *= 0.25;
        double vi = 0.0, vl = 0.0;
        for (int e = 0; e < E_; e++) {
            double d = imp[e] - mi; vi += d*d;
            d = lod[e] - ml;        vl += d*d;
        }
        vi *= 0.25; vl *= 0.25;
        double loss = vi / (mi*mi + 1e-10) + vl / (ml*ml + 1e-10);
        if (out_size > NTOK*C_) out[NTOK*C_] = (float)loss;
    }
}

// ---------------- launch ----------------
extern "C" void kernel_launch(void* const* d_in, const int* in_sizes, int n_in,
                              void* d_out, int out_size) {
    (void)in_sizes; (void)n_in;
    const float* x      = (const float*)d_in[0];
    const float* sp     = (const float*)d_in[2];
    const float* w_lin  = (const float*)d_in[3];
    const float* b_lin  = (const float*)d_in[4];
    const float* w_conv = (const float*)d_in[5];
    const float* w_gate = (const float*)d_in[6];
    const float* w1     = (const float*)d_in[7];
    const float* b1     = (const float*)d_in[8];
    const float* w2     = (const float*)d_in[9];
    const float* b2     = (const float*)d_in[10];
    float* out = (float*)d_out;

    cudaFuncSetAttribute(k_main, cudaFuncAttributeMaxDynamicSharedMemorySize, SMEM_MAIN);

    int prep_total = 32*64 + E_*32*JP + E_*96*64;
    k_prep<<<(prep_total + 255)/256, 256>>>(w_conv, w1, w2);
    k_emb<<<B_*C_, 256>>>(x);
    k_pw<<<B_, 64>>>(w_lin, b_lin);
    k_gate<<<NBLK, GA_TPB>>>(x, sp, w_gate);
    k_main<<<GRID_MAIN, TPB, SMEM_MAIN>>>(x, b1, b2, out);
    k_loss<<<1, 128>>>(out, out_size);
}